// round 7
// baseline (speedup 1.0000x reference)
#include <cuda_runtime.h>
#include <math.h>

// ---------------- problem constants ----------------
#define DIN     32
#define KLEN    512
#define PDIM    64
#define DMODEL  128
#define NLAYERS 4
#define PLEN    8
#define STRIDE  4
#define DI2     256
#define DSTATE  16
#define DCONV   4
#define DTRANK  8
#define NSEQ    127
#define BATCH   32
#define MROWS   (BATCH*PDIM)     // 2048
#define RTOT    (MROWS*NSEQ)     // 260096

// ---------------- scratch ----------------
__device__ float g_h[BATCH*KLEN*PDIM];
__device__ float g_e[RTOT*DMODEL];
__device__ float g_ah[RTOT*DMODEL];         // rms(e)*norm_w  hi (tf32)
__device__ float g_al[RTOT*DMODEL];         // lo
__device__ float g_uz[RTOT*2*DI2];
__device__ float g_yh[RTOT*DI2];            // scan output hi
__device__ float g_yl[RTOT*DI2];            // lo
__device__ float g_wins[NLAYERS*DMODEL*2*DI2*2];   // in_w pre-split+permuted tiles
__device__ float g_wouts[NLAYERS*DI2*DMODEL*2];    // out_w pre-split+permuted tiles
__device__ float g_val[MROWS];

// ---------------- helpers ----------------
__device__ __forceinline__ float tf32_rna(float v) {
    unsigned u; asm("cvt.rna.tf32.f32 %0, %1;" : "=r"(u) : "f"(v));
    return __uint_as_float(u);
}
__device__ __forceinline__ void mma_tf32(float* d, const unsigned* a, const unsigned* b) {
    asm volatile(
        "mma.sync.aligned.m16n8k8.row.col.f32.tf32.tf32.f32 "
        "{%0,%1,%2,%3}, {%4,%5,%6,%7}, {%8,%9}, {%0,%1,%2,%3};\n"
        : "+f"(d[0]), "+f"(d[1]), "+f"(d[2]), "+f"(d[3])
        : "r"(a[0]), "r"(a[1]), "r"(a[2]), "r"(a[3]), "r"(b[0]), "r"(b[1]));
}

// ---------------- 1. x@proj_w + b, LayerNorm ----------------
__global__ void k_proj_ln(const float* __restrict__ x, const float* __restrict__ pw,
                          const float* __restrict__ pb, const float* __restrict__ lw,
                          const float* __restrict__ lb) {
    int row = blockIdx.x;
    int t = threadIdx.x;
    __shared__ float xs[DIN];
    __shared__ float r1[64], r2[64];
    if (t < DIN) xs[t] = x[row*DIN + t];
    __syncthreads();
    float acc = pb[t];
#pragma unroll
    for (int i = 0; i < DIN; i++) acc = fmaf(xs[i], pw[i*PDIM + t], acc);
    r1[t] = acc; r2[t] = acc*acc;
    __syncthreads();
    for (int o = 32; o; o >>= 1) {
        if (t < o) { r1[t] += r1[t+o]; r2[t] += r2[t+o]; }
        __syncthreads();
    }
    float mu  = r1[0] * (1.f/64.f);
    float var = r2[0] * (1.f/64.f) - mu*mu;
    g_h[row*PDIM + t] = (acc - mu) * rsqrtf(var + 1e-5f) * lw[t] + lb[t];
}

// ---------------- 2. patch embed ----------------
__global__ void k_patch(const float* __restrict__ pw, const float* __restrict__ pb) {
    int n = blockIdx.x, m = blockIdx.y;
    int t = threadIdx.x;
    __shared__ float hv[PLEN];
    int b = m >> 6, pd = m & 63;
    if (t < PLEN) hv[t] = g_h[(b*KLEN + n*STRIDE + t)*PDIM + pd];
    __syncthreads();
    float acc = pb[t];
#pragma unroll
    for (int p = 0; p < PLEN; p++) acc = fmaf(hv[p], pw[p*DMODEL + t], acc);
    g_e[((size_t)m*NSEQ + n)*DMODEL + t] = acc;
}

// ---------------- 3. weight pre-split + pre-permute (GEMM B smem image) ----------------
__global__ void k_wsplit(const float* __restrict__ in_w, const float* __restrict__ out_w) {
    int idx = blockIdx.x*256 + threadIdx.x;
    if (idx < NLAYERS*DMODEL*512) {
        int l = idx >> 16;            // 65536/layer
        int e = idx & 65535;
        int k = e >> 9, n = e & 511;
        float w = in_w[idx];
        float H = tf32_rna(w), L = tf32_rna(w - H);
        int bx = n >> 7, nl = n & 127;
        int kt = k >> 4, kl = k & 15;
        int kg  = (kl & 3) | ((kl >> 3) << 2);
        int kgs = (kg + ((nl & 1) << 2)) & 7;
        int c   = (kl >> 2) & 1;
        size_t base = (size_t)l*131072 + (size_t)(bx*8 + kt)*4096 + (size_t)(nl*8 + kgs)*4;
        g_wins[base + c]     = H;
        g_wins[base + c + 2] = L;
    } else {
        int idx2 = idx - NLAYERS*DMODEL*512;
        if (idx2 < NLAYERS*DI2*DMODEL) {
            int l = idx2 >> 15;       // 32768/layer
            int e = idx2 & 32767;
            int k = e >> 7, n = e & 127;
            float w = out_w[idx2];
            float H = tf32_rna(w), L = tf32_rna(w - H);
            int kt = k >> 4, kl = k & 15;
            int kg  = (kl & 3) | ((kl >> 3) << 2);
            int kgs = (kg + ((n & 1) << 2)) & 7;
            int c   = (kl >> 2) & 1;
            size_t base = (size_t)l*65536 + (size_t)kt*4096 + (size_t)(n*8 + kgs)*4;
            g_wouts[base + c]     = H;
            g_wouts[base + c + 2] = L;
        }
    }
}

// ---------------- 4. rms + split (A operand, plain layout) ----------------
__global__ void k_rms_split(const float* __restrict__ nw) {
    int warp = threadIdx.x >> 5, lane = threadIdx.x & 31;
    int r = blockIdx.x*8 + warp;
    const float4* p = (const float4*)(g_e + (size_t)r*DMODEL);
    float4 v = p[lane];
    float s = v.x*v.x + v.y*v.y + v.z*v.z + v.w*v.w;
#pragma unroll
    for (int o = 16; o; o >>= 1) s += __shfl_xor_sync(0xffffffff, s, o);
    float rstd = rsqrtf(s*(1.f/DMODEL) + 1e-5f);
    float4 w4 = ((const float4*)nw)[lane];
    float4 h4, l4;
    float a;
    a = v.x*rstd*w4.x; h4.x = tf32_rna(a); l4.x = tf32_rna(a - h4.x);
    a = v.y*rstd*w4.y; h4.y = tf32_rna(a); l4.y = tf32_rna(a - h4.y);
    a = v.z*rstd*w4.z; h4.z = tf32_rna(a); l4.z = tf32_rna(a - h4.z);
    a = v.w*rstd*w4.w; h4.w = tf32_rna(a); l4.w = tf32_rna(a - h4.w);
    ((float4*)(g_ah + (size_t)r*DMODEL))[lane] = h4;
    ((float4*)(g_al + (size_t)r*DMODEL))[lane] = l4;
}

// ---------------- 5. 3xTF32 GEMM, vectorized fragments ----------------
// MODE 0: g_uz = split(rms(e)) @ in_w  (K=128, N=512)
// MODE 1: g_e += split(y) @ out_w     (K=256, N=128)
template<int MODE>
__global__ __launch_bounds__(256, 2) void k_gemm_tc(const float* __restrict__ Ah,
                                                    const float* __restrict__ Al,
                                                    const float* __restrict__ Bp,
                                                    float* __restrict__ C) {
    constexpr int N  = (MODE == 0) ? 512 : 128;
    constexpr int K  = (MODE == 0) ? 128 : 256;
    constexpr int KT = K/16;

    __shared__ __align__(16) float AsH[2048], AsL[2048], Bs[4096];

    int tid = threadIdx.x;
    int wid = tid >> 5, lane = tid & 31;
    int wm = wid >> 2, wn = wid & 3;          // 2x4 warps, warp tile 64x32
    int g = lane >> 2, tig = lane & 3;
    int row0 = blockIdx.y * 128;
    int bx = blockIdx.x;
    const float4* Bg = (const float4*)Bp + (size_t)bx*KT*1024;

    float acc[4][4][4];
#pragma unroll
    for (int mt = 0; mt < 4; mt++)
#pragma unroll
        for (int nt = 0; nt < 4; nt++)
#pragma unroll
            for (int j = 0; j < 4; j++) acc[mt][nt][j] = 0.f;

    int rA = tid >> 2;
    int kq = (tid & 3)*4;
    int jA = ((rA >> 3) & 1) | (((kq >> 2) & 1) << 1);   // invariant to +64
    int kqhi = (kq >> 3) << 2;
    int swzA = (rA & 1) << 2;

    for (int kt = 0; kt < KT; kt++) {
        int k0 = kt*16;
        // A stage: plain-split global -> permuted smem
#pragma unroll
        for (int s = 0; s < 2; s++) {
            int r = rA + s*64;
            float4 h4 = *(const float4*)&Ah[(size_t)(row0 + r)*K + k0 + kq];
            float4 l4 = *(const float4*)&Al[(size_t)(row0 + r)*K + k0 + kq];
            int rg = (r & 7) | ((r >> 4) << 3);
            float hv[4] = {h4.x, h4.y, h4.z, h4.w};
            float lv[4] = {l4.x, l4.y, l4.z, l4.w};
#pragma unroll
            for (int jj = 0; jj < 4; jj++) {
                int kgs = ((jj | kqhi) + swzA) & 7;
                int o = (rg*8 + kgs)*4 + jA;
                AsH[o] = hv[jj]; AsL[o] = lv[jj];
            }
        }
        // B stage: verbatim copy of pre-permuted tile
        {
            const float4* src = Bg + (size_t)kt*1024;
            float4* dst = (float4*)Bs;
#pragma unroll
            for (int s = 0; s < 4; s++) dst[tid + s*256] = src[tid + s*256];
        }
        __syncthreads();
#pragma unroll
        for (int ks = 0; ks < 2; ks++) {
            int kgs = ((tig | (ks << 2)) + ((g & 1) << 2)) & 7;
            float4 fH[4], fL[4];
#pragma unroll
            for (int mt = 0; mt < 4; mt++) {
                int rg = g | ((wm*4 + mt) << 3);
                fH[mt] = ((const float4*)AsH)[rg*8 + kgs];
                fL[mt] = ((const float4*)AsL)[rg*8 + kgs];
            }
#pragma unroll
            for (int nt = 0; nt < 4; nt++) {
                int nb = wn*32 + nt*8 + g;                 // nb&1 == g&1
                float4 fB = ((const float4*)Bs)[nb*8 + kgs];
                unsigned bH[2] = {__float_as_uint(fB.x), __float_as_uint(fB.y)};
                unsigned bL[2] = {__float_as_uint(fB.z), __float_as_uint(fB.w)};
#pragma unroll
                for (int mt = 0; mt < 4; mt++) {
                    unsigned aH[4] = {__float_as_uint(fH[mt].x), __float_as_uint(fH[mt].y),
                                      __float_as_uint(fH[mt].z), __float_as_uint(fH[mt].w)};
                    unsigned aL[4] = {__float_as_uint(fL[mt].x), __float_as_uint(fL[mt].y),
                                      __float_as_uint(fL[mt].z), __float_as_uint(fL[mt].w)};
                    mma_tf32(acc[mt][nt], aH, bH);
                    mma_tf32(acc[mt][nt], aL, bH);
                    mma_tf32(acc[mt][nt], aH, bL);
                }
            }
        }
        __syncthreads();
    }
#pragma unroll
    for (int mt = 0; mt < 4; mt++) {
#pragma unroll
        for (int nt = 0; nt < 4; nt++) {
            int r = row0 + wm*64 + mt*16 + g;
            int c = bx*128 + wn*32 + nt*8 + tig*2;
            float* p0 = &C[(size_t)r*N + c];
            float* p1 = &C[(size_t)(r+8)*N + c];
            if (MODE == 1) {
                p0[0] += acc[mt][nt][0]; p0[1] += acc[mt][nt][1];
                p1[0] += acc[mt][nt][2]; p1[1] += acc[mt][nt][3];
            } else {
                p0[0] = acc[mt][nt][0]; p0[1] = acc[mt][nt][1];
                p1[0] = acc[mt][nt][2]; p1[1] = acc[mt][nt][3];
            }
        }
    }
}

// ---------------- 6. fused conv+silu + xproj + dt + scan + silu(z), split y ----------------
#define SMEM_MID ((40*260 + 32*260 + 32*40)*4)   // xwT + uS + dbcS = 83200 B

__global__ __launch_bounds__(256) void k_mid(
    const float* __restrict__ xw, const float* __restrict__ dtw, const float* __restrict__ dtb,
    const float* __restrict__ cw, const float* __restrict__ cb,
    const float* __restrict__ alog, const float* __restrict__ dp)
{
    extern __shared__ float sm[];
    float* xwT  = sm;                   // [40][260] transposed xproj_w (pitch 260)
    float* uS   = sm + 40*260;          // [32][260]
    float* dbcS = uS + 32*260;          // [32][40]

    int m = blockIdx.x, tid = threadIdx.x;
    int rloc = tid >> 3, cg = tid & 7;

    for (int i = tid; i < 256*40; i += 256) {
        int k = i/40, c = i - k*40;
        xwT[c*260 + k] = xw[i];
    }

    float w0 = cw[tid*4+0], w1 = cw[tid*4+1], w2 = cw[tid*4+2], w3 = cw[tid*4+3];
    float cbv = cb[tid];
    float dw[8];
#pragma unroll
    for (int k = 0; k < 8; k++) dw[k] = dtw[k*DI2 + tid];
    float db = dtb[tid];
    float A[16];
#pragma unroll
    for (int s = 0; s < 16; s++) A[s] = -__expf(alog[tid*16 + s]);
    float A0 = A[0];
    bool fast = true;
#pragma unroll
    for (int s = 1; s < 16; s++) {
        float tgt = (float)(s+1)*A0;
        if (fabsf(A[s] - tgt) > 1e-4f*fabsf(tgt)) fast = false;
    }
    float Dv = dp[tid];
    float h[16];
#pragma unroll
    for (int s = 0; s < 16; s++) h[s] = 0.f;
    float x0 = 0.f, x1 = 0.f, x2 = 0.f;
    const float* uz = g_uz + (size_t)m*NSEQ*512;
    float* yph = g_yh + (size_t)m*NSEQ*DI2;
    float* ypl = g_yl + (size_t)m*NSEQ*DI2;
    __syncthreads();

    for (int n0 = 0; n0 < NSEQ; n0 += 32) {
        // --- conv + silu ---
#pragma unroll 8
        for (int n = 0; n < 32; n++) {
            if (n0 + n < NSEQ) {
                float x3 = uz[(size_t)(n0+n)*512 + tid];
                float v = fmaf(x0, w0, fmaf(x1, w1, fmaf(x2, w2, fmaf(x3, w3, cbv))));
                uS[n*260 + tid] = v * (1.f/(1.f + __expf(-v)));
                x0 = x1; x1 = x2; x2 = x3;
            }
        }
        __syncthreads();
        // --- xproj 256 -> 40, vectorized ---
        if (n0 + rloc < NSEQ) {
            float acc5[5] = {0.f, 0.f, 0.f, 0.f, 0.f};
            const float4* ur4 = (const float4*)(uS + rloc*260);
#pragma unroll 8
            for (int k4 = 0; k4 < 64; k4++) {
                float4 a4 = ur4[k4];
#pragma unroll
                for (int u = 0; u < 5; u++) {
                    float4 w4 = ((const float4*)(xwT + (cg*5 + u)*260))[k4];
                    acc5[u] += a4.x*w4.x + a4.y*w4.y + a4.z*w4.z + a4.w*w4.w;
                }
            }
#pragma unroll
            for (int u = 0; u < 5; u++) dbcS[rloc*40 + cg*5 + u] = acc5[u];
        }
        __syncthreads();
        // --- delta + scan + silu(z) ---
        for (int n = 0; n < 32; n++) {
            if (n0 + n < NSEQ) {
                const float4* dbc4 = (const float4*)(dbcS + n*40);
                float dt[8];
                *(float4*)&dt[0] = dbc4[0]; *(float4*)&dt[4] = dbc4[1];
                float bb[16], cc[16];
                *(float4*)&bb[0]  = dbc4[2]; *(float4*)&bb[4]  = dbc4[3];
                *(float4*)&bb[8]  = dbc4[4]; *(float4*)&bb[12] = dbc4[5];
                *(float4*)&cc[0]  = dbc4[6]; *(float4*)&cc[4]  = dbc4[7];
                *(float4*)&cc[8]  = dbc4[8]; *(float4*)&cc[12] = dbc4[9];
                float sdt = db;
#pragma unroll
                for (int k = 0; k < 8; k++) sdt = fmaf(dt[k], dw[k], sdt);
                float d = (sdt > 20.f) ? sdt : log1pf(__expf(sdt));
                float u = uS[n*260 + tid];
                float dlu = d*u;
                float a0 = 0.f, a1 = 0.f, a2 = 0.f, a3 = 0.f;
                if (fast) {
                    float q = __expf(d*A0);
                    float q2 = q*q, q3 = q2*q, q4 = q2*q2;
                    float q8 = q4*q4, q12 = q8*q4;
                    float pl[4] = {q, q2, q3, q4};
                    float pe[4] = {1.f, q4, q8, q12};
#pragma unroll
                    for (int s = 0; s < 16; s++) {
                        float p = pe[s>>2]*pl[s&3];
                        h[s] = fmaf(p, h[s], dlu*bb[s]);
                        float t = h[s]*cc[s];
                        if      ((s&3) == 0) a0 += t;
                        else if ((s&3) == 1) a1 += t;
                        else if ((s&3) == 2) a2 += t;
                        else                 a3 += t;
                    }
                } else {
#pragma unroll
                    for (int s = 0; s < 16; s++) {
                        float dA = __expf(d*A[s]);
                        h[s] = fmaf(dA, h[s], dlu*bb[s]);
                        float t = h[s]*cc[s];
                        if      ((s&3) == 0) a0 += t;
                        else if ((s&3) == 1) a1 += t;
                        else if ((s&3) == 2) a2 += t;
                        else                 a3 += t;
                    }
                }
                float accy = (a0 + a1) + (a2 + a3);
                float z = uz[(size_t)(n0+n)*512 + DI2 + tid];
                float sz = z / (1.f + __expf(-z));
                float yv = (accy + u*Dv) * sz;
                float yh = tf32_rna(yv);
                size_t o = (size_t)(n0+n)*DI2 + tid;
                yph[o] = yh;
                ypl[o] = tf32_rna(yv - yh);
            }
        }
        __syncthreads();
    }
}

// ---------------- 7. final rms + bb dot ----------------
__global__ void k_final(const float* __restrict__ fnw, const float* __restrict__ bbw,
                        const float* __restrict__ bbb) {
    int m = blockIdx.x, t = threadIdx.x;   // 128 threads
    int w = t >> 5, lane = t & 31;
    __shared__ float rstdS[NSEQ];
    for (int n = w; n < NSEQ; n += 4) {
        const float* p = g_e + ((size_t)m*NSEQ + n)*DMODEL;
        float s = 0.f;
#pragma unroll
        for (int i = 0; i < 4; i++) { float v = p[lane + 32*i]; s = fmaf(v, v, s); }
#pragma unroll
        for (int o = 16; o; o >>= 1) s += __shfl_xor_sync(0xffffffff, s, o);
        if (lane == 0) rstdS[n] = rsqrtf(s*(1.f/DMODEL) + 1e-5f);
    }
    __syncthreads();
    float fn = fnw[t];
    float acc = 0.f;
    const float* ep = g_e + (size_t)m*NSEQ*DMODEL + t;
#pragma unroll 4
    for (int n = 0; n < NSEQ; n++)
        acc = fmaf(ep[(size_t)n*DMODEL]*rstdS[n]*fn, bbw[n*DMODEL + t], acc);
#pragma unroll
    for (int o = 16; o; o >>= 1) acc += __shfl_xor_sync(0xffffffff, acc, o);
    __shared__ float fr[4];
    if (lane == 0) fr[w] = acc;
    __syncthreads();
    if (t == 0) g_val[m] = fr[0] + fr[1] + fr[2] + fr[3] + bbb[0];
}

// ---------------- 8. head ----------------
__global__ void k_head(const float* __restrict__ hw, const float* __restrict__ hb,
                       float* __restrict__ out) {
    int t = threadIdx.x;  // 64
    int b = t >> 1, o = t & 1;
    float s = hb[o];
    for (int pd = 0; pd < 64; pd++) s = fmaf(g_val[b*64 + pd], hw[pd*2 + o], s);
    out[t] = s;
}

// ---------------- launch ----------------
extern "C" void kernel_launch(void* const* d_in, const int* in_sizes, int n_in,
                              void* d_out, int out_size) {
    const float* x       = (const float*)d_in[0];
    const float* proj_w  = (const float*)d_in[1];
    const float* proj_b  = (const float*)d_in[2];
    const float* ln_w    = (const float*)d_in[3];
    const float* ln_b    = (const float*)d_in[4];
    const float* patch_w = (const float*)d_in[5];
    const float* patch_b = (const float*)d_in[6];
    const float* in_w    = (const float*)d_in[7];
    const float* conv_w  = (const float*)d_in[8];
    const float* conv_b  = (const float*)d_in[9];
    const float* xproj_w = (const float*)d_in[10];
    const float* dt_w    = (const float*)d_in[11];
    const float* dt_b    = (const float*)d_in[12];
    const float* A_log   = (const float*)d_in[13];
    const float* Dp      = (const float*)d_in[14];
    const float* out_w   = (const float*)d_in[15];
    const float* norm_w  = (const float*)d_in[16];
    const float* fnorm_w = (const float*)d_in[17];
    const float* bb_w    = (const float*)d_in[18];
    const float* bb_b    = (const float*)d_in[19];
    const float* head_w  = (const float*)d_in[20];
    const float* head_b  = (const float*)d_in[21];

    cudaFuncSetAttribute(k_mid, cudaFuncAttributeMaxDynamicSharedMemorySize, SMEM_MID);

    float *d_ah, *d_al, *d_yh, *d_yl, *d_win, *d_wout, *d_uzp, *d_ep;
    cudaGetSymbolAddress((void**)&d_ah, g_ah);
    cudaGetSymbolAddress((void**)&d_al, g_al);
    cudaGetSymbolAddress((void**)&d_yh, g_yh);
    cudaGetSymbolAddress((void**)&d_yl, g_yl);
    cudaGetSymbolAddress((void**)&d_win, g_wins);
    cudaGetSymbolAddress((void**)&d_wout, g_wouts);
    cudaGetSymbolAddress((void**)&d_uzp, g_uz);
    cudaGetSymbolAddress((void**)&d_ep, g_e);

    k_proj_ln<<<BATCH*KLEN, 64>>>(x, proj_w, proj_b, ln_w, ln_b);
    k_patch<<<dim3(NSEQ, MROWS), DMODEL>>>(patch_w, patch_b);
    k_wsplit<<<(NLAYERS*(65536+32768))/256, 256>>>(in_w, out_w);

    for (int l = 0; l < NLAYERS; l++) {
        k_rms_split<<<RTOT/8, 256>>>(norm_w + l*DMODEL);
        k_gemm_tc<0><<<dim3(4, RTOT/128), 256>>>(d_ah, d_al,
                                                 d_win + (size_t)l*131072, d_uzp);
        k_mid<<<MROWS, 256, SMEM_MID>>>(xproj_w + l*DI2*40, dt_w + l*DTRANK*DI2, dt_b + l*DI2,
                                        conv_w + l*DI2*DCONV, conv_b + l*DI2,
                                        A_log + l*DI2*DSTATE, Dp + l*DI2);
        k_gemm_tc<1><<<dim3(1, RTOT/128), 256>>>(d_yh, d_yl,
                                                 d_wout + (size_t)l*65536, d_ep);
    }

    k_final<<<MROWS, DMODEL>>>(fnorm_w, bb_w, bb_b);
    k_head<<<1, 64>>>(head_w, head_b, (float*)d_out);
}

// round 8
// speedup vs baseline: 1.3495x; 1.3495x over previous
#include <cuda_runtime.h>
#include <math.h>

// ---------------- problem constants ----------------
#define DIN     32
#define KLEN    512
#define PDIM    64
#define DMODEL  128
#define NLAYERS 4
#define PLEN    8
#define STRIDE  4
#define DI2     256
#define DSTATE  16
#define DCONV   4
#define DTRANK  8
#define NSEQ    127
#define BATCH   32
#define MROWS   (BATCH*PDIM)     // 2048
#define RTOT    (MROWS*NSEQ)     // 260096

// ---------------- scratch ----------------
__device__ float g_h[BATCH*KLEN*PDIM];
__device__ float g_e[RTOT*DMODEL];
__device__ float g_rstd[RTOT];
__device__ float g_uz[RTOT*2*DI2];
__device__ float g_y[RTOT*DI2];
__device__ float g_wins[NLAYERS*DMODEL*2*DI2*2];   // in_w pre-split+permuted tiles
__device__ float g_wouts[NLAYERS*DI2*DMODEL*2];    // out_w pre-split+permuted tiles
__device__ float g_val[MROWS];

// ---------------- helpers ----------------
__device__ __forceinline__ float tf32_rna(float v) {
    unsigned u; asm("cvt.rna.tf32.f32 %0, %1;" : "=r"(u) : "f"(v));
    return __uint_as_float(u);
}
__device__ __forceinline__ void mma_tf32(float* d, const unsigned* a, const unsigned* b) {
    asm volatile(
        "mma.sync.aligned.m16n8k8.row.col.f32.tf32.tf32.f32 "
        "{%0,%1,%2,%3}, {%4,%5,%6,%7}, {%8,%9}, {%0,%1,%2,%3};\n"
        : "+f"(d[0]), "+f"(d[1]), "+f"(d[2]), "+f"(d[3])
        : "r"(a[0]), "r"(a[1]), "r"(a[2]), "r"(a[3]), "r"(b[0]), "r"(b[1]));
}

// ---------------- 1. x@proj_w + b, LayerNorm ----------------
__global__ void k_proj_ln(const float* __restrict__ x, const float* __restrict__ pw,
                          const float* __restrict__ pb, const float* __restrict__ lw,
                          const float* __restrict__ lb) {
    int row = blockIdx.x;
    int t = threadIdx.x;
    __shared__ float xs[DIN];
    __shared__ float r1[64], r2[64];
    if (t < DIN) xs[t] = x[row*DIN + t];
    __syncthreads();
    float acc = pb[t];
#pragma unroll
    for (int i = 0; i < DIN; i++) acc = fmaf(xs[i], pw[i*PDIM + t], acc);
    r1[t] = acc; r2[t] = acc*acc;
    __syncthreads();
    for (int o = 32; o; o >>= 1) {
        if (t < o) { r1[t] += r1[t+o]; r2[t] += r2[t+o]; }
        __syncthreads();
    }
    float mu  = r1[0] * (1.f/64.f);
    float var = r2[0] * (1.f/64.f) - mu*mu;
    g_h[row*PDIM + t] = (acc - mu) * rsqrtf(var + 1e-5f) * lw[t] + lb[t];
}

// ---------------- 2. patch embed ----------------
__global__ void k_patch(const float* __restrict__ pw, const float* __restrict__ pb) {
    int n = blockIdx.x, m = blockIdx.y;
    int t = threadIdx.x;
    __shared__ float hv[PLEN];
    int b = m >> 6, pd = m & 63;
    if (t < PLEN) hv[t] = g_h[(b*KLEN + n*STRIDE + t)*PDIM + pd];
    __syncthreads();
    float acc = pb[t];
#pragma unroll
    for (int p = 0; p < PLEN; p++) acc = fmaf(hv[p], pw[p*DMODEL + t], acc);
    g_e[((size_t)m*NSEQ + n)*DMODEL + t] = acc;
}

// ---------------- 3. weight pre-split + pre-permute (verified in R7) ----------------
__global__ void k_wsplit(const float* __restrict__ in_w, const float* __restrict__ out_w) {
    int idx = blockIdx.x*256 + threadIdx.x;
    if (idx < NLAYERS*DMODEL*512) {
        int l = idx >> 16;
        int e = idx & 65535;
        int k = e >> 9, n = e & 511;
        float w = in_w[idx];
        float H = tf32_rna(w), L = tf32_rna(w - H);
        int bx = n >> 7, nl = n & 127;
        int kt = k >> 4, kl = k & 15;
        int kg  = (kl & 3) | ((kl >> 3) << 2);
        int kgs = (kg + ((nl & 1) << 2)) & 7;
        int c   = (kl >> 2) & 1;
        size_t base = (size_t)l*131072 + (size_t)(bx*8 + kt)*4096 + (size_t)(nl*8 + kgs)*4;
        g_wins[base + c]     = H;
        g_wins[base + c + 2] = L;
    } else {
        int idx2 = idx - NLAYERS*DMODEL*512;
        if (idx2 < NLAYERS*DI2*DMODEL) {
            int l = idx2 >> 15;
            int e = idx2 & 32767;
            int k = e >> 7, n = e & 127;
            float w = out_w[idx2];
            float H = tf32_rna(w), L = tf32_rna(w - H);
            int kt = k >> 4, kl = k & 15;
            int kg  = (kl & 3) | ((kl >> 3) << 2);
            int kgs = (kg + ((n & 1) << 2)) & 7;
            int c   = (kl >> 2) & 1;
            size_t base = (size_t)l*65536 + (size_t)kt*4096 + (size_t)(n*8 + kgs)*4;
            g_wouts[base + c]     = H;
            g_wouts[base + c + 2] = L;
        }
    }
}

// ---------------- 4. per-row rms factor ----------------
__global__ void k_rms() {
    int warp = threadIdx.x >> 5, lane = threadIdx.x & 31;
    int r = blockIdx.x*8 + warp;
    const float4* p = (const float4*)(g_e + (size_t)r*DMODEL);
    float4 v = p[lane];
    float s = v.x*v.x + v.y*v.y + v.z*v.z + v.w*v.w;
#pragma unroll
    for (int o = 16; o; o >>= 1) s += __shfl_xor_sync(0xffffffff, s, o);
    if (lane == 0) g_rstd[r] = rsqrtf(s*(1.f/DMODEL) + 1e-5f);
}

// ---------------- 5. 3xTF32 GEMM, vectorized fragments, in-kernel split ----------------
// MODE 0: g_uz = (rms(e)*norm_w) @ in_w  (K=128, N=512)
// MODE 1: g_e += y @ out_w               (K=256, N=128)
template<int MODE>
__global__ __launch_bounds__(256, 2) void k_gemm_tc(const float* __restrict__ A,
                                                    const float* __restrict__ colScale,
                                                    const float* __restrict__ Bp,
                                                    float* __restrict__ C) {
    constexpr int N  = (MODE == 0) ? 512 : 128;
    constexpr int K  = (MODE == 0) ? 128 : 256;
    constexpr int KT = K/16;

    __shared__ __align__(16) float AsH[2048], AsL[2048], Bs[4096];

    int tid = threadIdx.x;
    int wid = tid >> 5, lane = tid & 31;
    int wm = wid >> 2, wn = wid & 3;          // 2x4 warps, warp tile 64x32
    int g = lane >> 2, tig = lane & 3;
    int row0 = blockIdx.y * 128;
    int bx = blockIdx.x;
    const float4* Bg = (const float4*)Bp + (size_t)bx*KT*1024;

    float acc[4][4][4];
#pragma unroll
    for (int mt = 0; mt < 4; mt++)
#pragma unroll
        for (int nt = 0; nt < 4; nt++)
#pragma unroll
            for (int j = 0; j < 4; j++) acc[mt][nt][j] = 0.f;

    int rA = tid >> 2;
    int kq = (tid & 3)*4;
    int jA = ((rA >> 3) & 1) | (((kq >> 2) & 1) << 1);
    int kqhi = (kq >> 3) << 2;
    int swzA = (rA & 1) << 2;

    for (int kt = 0; kt < KT; kt++) {
        int k0 = kt*16;
        // A stage: fp32 global -> scale -> split -> permuted smem
#pragma unroll
        for (int s = 0; s < 2; s++) {
            int r = rA + s*64;
            float4 v4 = *(const float4*)&A[(size_t)(row0 + r)*K + k0 + kq];
            float vv[4] = {v4.x, v4.y, v4.z, v4.w};
            if (MODE == 0) {
                float rs = g_rstd[row0 + r];
#pragma unroll
                for (int j = 0; j < 4; j++) vv[j] *= rs * colScale[k0 + kq + j];
            }
            int rg = (r & 7) | ((r >> 4) << 3);
#pragma unroll
            for (int jj = 0; jj < 4; jj++) {
                float hf = tf32_rna(vv[jj]);
                float lf = tf32_rna(vv[jj] - hf);
                int kgs = ((jj | kqhi) + swzA) & 7;
                int o = (rg*8 + kgs)*4 + jA;
                AsH[o] = hf; AsL[o] = lf;
            }
        }
        // B stage: verbatim copy of pre-permuted tile
        {
            const float4* src = Bg + (size_t)kt*1024;
            float4* dst = (float4*)Bs;
#pragma unroll
            for (int s = 0; s < 4; s++) dst[tid + s*256] = src[tid + s*256];
        }
        __syncthreads();
#pragma unroll
        for (int ks = 0; ks < 2; ks++) {
            int kgs = ((tig | (ks << 2)) + ((g & 1) << 2)) & 7;
            float4 fH[4], fL[4];
#pragma unroll
            for (int mt = 0; mt < 4; mt++) {
                int rg = g | ((wm*4 + mt) << 3);
                fH[mt] = ((const float4*)AsH)[rg*8 + kgs];
                fL[mt] = ((const float4*)AsL)[rg*8 + kgs];
            }
#pragma unroll
            for (int nt = 0; nt < 4; nt++) {
                int nb = wn*32 + nt*8 + g;
                float4 fB = ((const float4*)Bs)[nb*8 + kgs];
                unsigned bH[2] = {__float_as_uint(fB.x), __float_as_uint(fB.y)};
                unsigned bL[2] = {__float_as_uint(fB.z), __float_as_uint(fB.w)};
#pragma unroll
                for (int mt = 0; mt < 4; mt++) {
                    unsigned aH[4] = {__float_as_uint(fH[mt].x), __float_as_uint(fH[mt].y),
                                      __float_as_uint(fH[mt].z), __float_as_uint(fH[mt].w)};
                    unsigned aL[4] = {__float_as_uint(fL[mt].x), __float_as_uint(fL[mt].y),
                                      __float_as_uint(fL[mt].z), __float_as_uint(fL[mt].w)};
                    mma_tf32(acc[mt][nt], aH, bH);
                    mma_tf32(acc[mt][nt], aL, bH);
                    mma_tf32(acc[mt][nt], aH, bL);
                }
            }
        }
        __syncthreads();
    }
#pragma unroll
    for (int mt = 0; mt < 4; mt++) {
#pragma unroll
        for (int nt = 0; nt < 4; nt++) {
            int r = row0 + wm*64 + mt*16 + g;
            int c = bx*128 + wn*32 + nt*8 + tig*2;
            float* p0 = &C[(size_t)r*N + c];
            float* p1 = &C[(size_t)(r+8)*N + c];
            if (MODE == 1) {
                p0[0] += acc[mt][nt][0]; p0[1] += acc[mt][nt][1];
                p1[0] += acc[mt][nt][2]; p1[1] += acc[mt][nt][3];
            } else {
                p0[0] = acc[mt][nt][0]; p0[1] = acc[mt][nt][1];
                p1[0] = acc[mt][nt][2]; p1[1] = acc[mt][nt][3];
            }
        }
    }
}

// ---------------- 6. fused conv+silu + xproj + dt + scan + silu(z) ----------------
// smem: xwT[40][260] + uS[32][260] + zS[32][260] + dbcS[32][40] = 116 KB dyn
#define SMEM_MID ((40*260 + 32*260 + 32*260 + 32*40)*4)

__global__ __launch_bounds__(256, 2) void k_mid(
    const float* __restrict__ xw, const float* __restrict__ dtw, const float* __restrict__ dtb,
    const float* __restrict__ cw, const float* __restrict__ cb,
    const float* __restrict__ alog, const float* __restrict__ dp)
{
    extern __shared__ float sm[];
    float* xwT  = sm;                   // [40][260]
    float* uS   = sm + 40*260;          // [32][260]
    float* zS   = uS + 32*260;          // [32][260]
    float* dbcS = zS + 32*260;          // [32][40]

    int m = blockIdx.x, tid = threadIdx.x;
    int rloc = tid >> 3, cg = tid & 7;

    for (int i = tid; i < 256*40; i += 256) {
        int k = i/40, c = i - k*40;
        xwT[c*260 + k] = xw[i];
    }

    float w0 = cw[tid*4+0], w1 = cw[tid*4+1], w2 = cw[tid*4+2], w3 = cw[tid*4+3];
    float cbv = cb[tid];
    float dw[8];
#pragma unroll
    for (int k = 0; k < 8; k++) dw[k] = dtw[k*DI2 + tid];
    float db = dtb[tid];
    float A[16];
#pragma unroll
    for (int s = 0; s < 16; s++) A[s] = -__expf(alog[tid*16 + s]);
    float A0 = A[0];
    bool fast = true;
#pragma unroll
    for (int s = 1; s < 16; s++) {
        float tgt = (float)(s+1)*A0;
        if (fabsf(A[s] - tgt) > 1e-4f*fabsf(tgt)) fast = false;
    }
    float Dv = dp[tid];
    float h[16];
#pragma unroll
    for (int s = 0; s < 16; s++) h[s] = 0.f;
    float x0 = 0.f, x1 = 0.f, x2 = 0.f;
    const float* uz = g_uz + (size_t)m*NSEQ*512;
    float* yp = g_y + (size_t)m*NSEQ*DI2;
    __syncthreads();

    for (int n0 = 0; n0 < NSEQ; n0 += 32) {
        int CN = min(32, NSEQ - n0);
        // --- batched loads: u chunk -> regs, z chunk -> smem (MLP ~64) ---
        float xv[32];
#pragma unroll
        for (int n = 0; n < 32; n++)
            xv[n] = (n < CN) ? uz[(size_t)(n0+n)*512 + tid] : 0.f;
#pragma unroll
        for (int n = 0; n < 32; n++)
            zS[n*260 + tid] = (n < CN) ? uz[(size_t)(n0+n)*512 + DI2 + tid] : 0.f;
        // --- conv + silu from registers ---
#pragma unroll
        for (int n = 0; n < 32; n++) {
            float v = fmaf(x0, w0, fmaf(x1, w1, fmaf(x2, w2, fmaf(xv[n], w3, cbv))));
            uS[n*260 + tid] = v * (1.f/(1.f + __expf(-v)));
            x0 = x1; x1 = x2; x2 = xv[n];
        }
        __syncthreads();
        // --- xproj 256 -> 40, vectorized ---
        if (rloc < CN) {
            float acc5[5] = {0.f, 0.f, 0.f, 0.f, 0.f};
            const float4* ur4 = (const float4*)(uS + rloc*260);
#pragma unroll 8
            for (int k4 = 0; k4 < 64; k4++) {
                float4 a4 = ur4[k4];
#pragma unroll
                for (int u = 0; u < 5; u++) {
                    float4 w4 = ((const float4*)(xwT + (cg*5 + u)*260))[k4];
                    acc5[u] += a4.x*w4.x + a4.y*w4.y + a4.z*w4.z + a4.w*w4.w;
                }
            }
#pragma unroll
            for (int u = 0; u < 5; u++) dbcS[rloc*40 + cg*5 + u] = acc5[u];
        }
        __syncthreads();
        // --- delta + scan + silu(z) ---
        for (int n = 0; n < CN; n++) {
            const float4* dbc4 = (const float4*)(dbcS + n*40);
            float dt[8];
            *(float4*)&dt[0] = dbc4[0]; *(float4*)&dt[4] = dbc4[1];
            float bb[16], cc[16];
            *(float4*)&bb[0]  = dbc4[2]; *(float4*)&bb[4]  = dbc4[3];
            *(float4*)&bb[8]  = dbc4[4]; *(float4*)&bb[12] = dbc4[5];
            *(float4*)&cc[0]  = dbc4[6]; *(float4*)&cc[4]  = dbc4[7];
            *(float4*)&cc[8]  = dbc4[8]; *(float4*)&cc[12] = dbc4[9];
            float sdt = db;
#pragma unroll
            for (int k = 0; k < 8; k++) sdt = fmaf(dt[k], dw[k], sdt);
            float d = (sdt > 20.f) ? sdt : log1pf(__expf(sdt));
            float u = uS[n*260 + tid];
            float dlu = d*u;
            float a0 = 0.f, a1 = 0.f, a2 = 0.f, a3 = 0.f;
            if (fast) {
                float q = __expf(d*A0);
                float q2 = q*q, q3 = q2*q, q4 = q2*q2;
                float q8 = q4*q4, q12 = q8*q4;
                float pl[4] = {q, q2, q3, q4};
                float pe[4] = {1.f, q4, q8, q12};
#pragma unroll
                for (int s = 0; s < 16; s++) {
                    float p = pe[s>>2]*pl[s&3];
                    h[s] = fmaf(p, h[s], dlu*bb[s]);
                    float t = h[s]*cc[s];
                    if      ((s&3) == 0) a0 += t;
                    else if ((s&3) == 1) a1 += t;
                    else if ((s&3) == 2) a2 += t;
                    else                 a3 += t;
                }
            } else {
#pragma unroll
                for (int s = 0; s < 16; s++) {
                    float dA = __expf(d*A[s]);
                    h[s] = fmaf(dA, h[s], dlu*bb[s]);
                    float t = h[s]*cc[s];
                    if      ((s&3) == 0) a0 += t;
                    else if ((s&3) == 1) a1 += t;
                    else if ((s&3) == 2) a2 += t;
                    else                 a3 += t;
                }
            }
            float accy = (a0 + a1) + (a2 + a3);
            float z = zS[n*260 + tid];
            float sz = z / (1.f + __expf(-z));
            yp[(size_t)(n0+n)*DI2 + tid] = (accy + u*Dv) * sz;
        }
        __syncthreads();
    }
}

// ---------------- 7. final rms + bb dot ----------------
__global__ void k_final(const float* __restrict__ fnw, const float* __restrict__ bbw,
                        const float* __restrict__ bbb) {
    int m = blockIdx.x, t = threadIdx.x;   // 128 threads
    int w = t >> 5, lane = t & 31;
    __shared__ float rstdS[NSEQ];
    for (int n = w; n < NSEQ; n += 4) {
        const float* p = g_e + ((size_t)m*NSEQ + n)*DMODEL;
        float s = 0.f;
#pragma unroll
        for (int i = 0; i < 4; i++) { float v = p[lane + 32*i]; s = fmaf(v, v, s); }
#pragma unroll
        for (int o = 16; o; o >>= 1) s += __shfl_xor_sync(0xffffffff, s, o);
        if (lane == 0) rstdS[n] = rsqrtf(s*(1.f/DMODEL) + 1e-5f);
    }
    __syncthreads();
    float fn = fnw[t];
    float acc = 0.f;
    const float* ep = g_e + (size_t)m*NSEQ*DMODEL + t;
#pragma unroll 4
    for (int n = 0; n < NSEQ; n++)
        acc = fmaf(ep[(size_t)n*DMODEL]*rstdS[n]*fn, bbw[n*DMODEL + t], acc);
#pragma unroll
    for (int o = 16; o; o >>= 1) acc += __shfl_xor_sync(0xffffffff, acc, o);
    __shared__ float fr[4];
    if (lane == 0) fr[w] = acc;
    __syncthreads();
    if (t == 0) g_val[m] = fr[0] + fr[1] + fr[2] + fr[3] + bbb[0];
}

// ---------------- 8. head ----------------
__global__ void k_head(const float* __restrict__ hw, const float* __restrict__ hb,
                       float* __restrict__ out) {
    int t = threadIdx.x;  // 64
    int b = t >> 1, o = t & 1;
    float s = hb[o];
    for (int pd = 0; pd < 64; pd++) s = fmaf(g_val[b*64 + pd], hw[pd*2 + o], s);
    out[t] = s;
}

// ---------------- launch ----------------
extern "C" void kernel_launch(void* const* d_in, const int* in_sizes, int n_in,
                              void* d_out, int out_size) {
    const float* x       = (const float*)d_in[0];
    const float* proj_w  = (const float*)d_in[1];
    const float* proj_b  = (const float*)d_in[2];
    const float* ln_w    = (const float*)d_in[3];
    const float* ln_b    = (const float*)d_in[4];
    const float* patch_w = (const float*)d_in[5];
    const float* patch_b = (const float*)d_in[6];
    const float* in_w    = (const float*)d_in[7];
    const float* conv_w  = (const float*)d_in[8];
    const float* conv_b  = (const float*)d_in[9];
    const float* xproj_w = (const float*)d_in[10];
    const float* dt_w    = (const float*)d_in[11];
    const float* dt_b    = (const float*)d_in[12];
    const float* A_log   = (const float*)d_in[13];
    const float* Dp      = (const float*)d_in[14];
    const float* out_w   = (const float*)d_in[15];
    const float* norm_w  = (const float*)d_in[16];
    const float* fnorm_w = (const float*)d_in[17];
    const float* bb_w    = (const float*)d_in[18];
    const float* bb_b    = (const float*)d_in[19];
    const float* head_w  = (const float*)d_in[20];
    const float* head_b  = (const float*)d_in[21];

    cudaFuncSetAttribute(k_mid, cudaFuncAttributeMaxDynamicSharedMemorySize, SMEM_MID);

    float *d_win, *d_wout, *d_uzp, *d_ep, *d_yp;
    cudaGetSymbolAddress((void**)&d_win, g_wins);
    cudaGetSymbolAddress((void**)&d_wout, g_wouts);
    cudaGetSymbolAddress((void**)&d_uzp, g_uz);
    cudaGetSymbolAddress((void**)&d_ep, g_e);
    cudaGetSymbolAddress((void**)&d_yp, g_y);

    k_proj_ln<<<BATCH*KLEN, 64>>>(x, proj_w, proj_b, ln_w, ln_b);
    k_patch<<<dim3(NSEQ, MROWS), DMODEL>>>(patch_w, patch_b);
    k_wsplit<<<(NLAYERS*(65536+32768))/256, 256>>>(in_w, out_w);

    for (int l = 0; l < NLAYERS; l++) {
        k_rms<<<RTOT/8, 256>>>();
        k_gemm_tc<0><<<dim3(4, RTOT/128), 256>>>(d_ep, norm_w + l*DMODEL,
                                                 d_win + (size_t)l*131072, d_uzp);
        k_mid<<<MROWS, 256, SMEM_MID>>>(xproj_w + l*DI2*40, dt_w + l*DTRANK*DI2, dt_b + l*DI2,
                                        conv_w + l*DI2*DCONV, conv_b + l*DI2,
                                        A_log + l*DI2*DSTATE, Dp + l*DI2);
        k_gemm_tc<1><<<dim3(1, RTOT/128), 256>>>(d_yp, nullptr,
                                                 d_wout + (size_t)l*65536, d_ep);
    }

    k_final<<<MROWS, DMODEL>>>(fnorm_w, bb_w, bb_b);
    k_head<<<1, 64>>>(head_w, head_b, (float*)d_out);
}

// round 10
// speedup vs baseline: 1.7944x; 1.3297x over previous
#include <cuda_runtime.h>
#include <math.h>

// ---------------- problem constants ----------------
#define DIN     32
#define KLEN    512
#define PDIM    64
#define DMODEL  128
#define NLAYERS 4
#define PLEN    8
#define STRIDE  4
#define DI2     256
#define DSTATE  16
#define DCONV   4
#define DTRANK  8
#define NSEQ    127
#define BATCH   32
#define MROWS   (BATCH*PDIM)     // 2048
#define RTOT    (MROWS*NSEQ)     // 260096

// ---------------- scratch ----------------
__device__ float g_h[BATCH*KLEN*PDIM];
__device__ float g_e[RTOT*DMODEL];
__device__ float g_rstd[RTOT];
__device__ float g_uz[RTOT*2*DI2];
__device__ float g_y[RTOT*DI2];
__device__ unsigned g_wins[NLAYERS*65536];   // in_w bf16-pair images (H/L interleaved)
__device__ unsigned g_wouts[NLAYERS*32768];  // out_w bf16-pair images
__device__ float g_val[MROWS];

// ---------------- helpers ----------------
__device__ __forceinline__ unsigned bf16pair(float v0, float v1) {
    unsigned p;
    asm("cvt.rn.bf16x2.f32 %0, %1, %2;" : "=r"(p) : "f"(v1), "f"(v0));
    return p;  // low16 = bf16(v0), high16 = bf16(v1)
}
__device__ __forceinline__ void bf16split(float v0, float v1, unsigned& hp, unsigned& lp) {
    hp = bf16pair(v0, v1);
    float r0 = v0 - __uint_as_float(hp << 16);
    float r1 = v1 - __uint_as_float(hp & 0xffff0000u);
    lp = bf16pair(r0, r1);
}
__device__ __forceinline__ void mma_bf16(float* d, const unsigned* a, const unsigned* b) {
    asm volatile(
        "mma.sync.aligned.m16n8k16.row.col.f32.bf16.bf16.f32 "
        "{%0,%1,%2,%3}, {%4,%5,%6,%7}, {%8,%9}, {%0,%1,%2,%3};\n"
        : "+f"(d[0]), "+f"(d[1]), "+f"(d[2]), "+f"(d[3])
        : "r"(a[0]), "r"(a[1]), "r"(a[2]), "r"(a[3]), "r"(b[0]), "r"(b[1]));
}

// ---------------- 1. x@proj_w + b, LayerNorm ----------------
__global__ void k_proj_ln(const float* __restrict__ x, const float* __restrict__ pw,
                          const float* __restrict__ pb, const float* __restrict__ lw,
                          const float* __restrict__ lb) {
    int row = blockIdx.x;
    int t = threadIdx.x;
    __shared__ float xs[DIN];
    __shared__ float r1[64], r2[64];
    if (t < DIN) xs[t] = x[row*DIN + t];
    __syncthreads();
    float acc = pb[t];
#pragma unroll
    for (int i = 0; i < DIN; i++) acc = fmaf(xs[i], pw[i*PDIM + t], acc);
    r1[t] = acc; r2[t] = acc*acc;
    __syncthreads();
    for (int o = 32; o; o >>= 1) {
        if (t < o) { r1[t] += r1[t+o]; r2[t] += r2[t+o]; }
        __syncthreads();
    }
    float mu  = r1[0] * (1.f/64.f);
    float var = r2[0] * (1.f/64.f) - mu*mu;
    g_h[row*PDIM + t] = (acc - mu) * rsqrtf(var + 1e-5f) * lw[t] + lb[t];
}

// ---------------- 2. patch embed ----------------
__global__ void k_patch(const float* __restrict__ pw, const float* __restrict__ pb) {
    int n = blockIdx.x, m = blockIdx.y;
    int t = threadIdx.x;
    __shared__ float hv[PLEN];
    int b = m >> 6, pd = m & 63;
    if (t < PLEN) hv[t] = g_h[(b*KLEN + n*STRIDE + t)*PDIM + pd];
    __syncthreads();
    float acc = pb[t];
#pragma unroll
    for (int p = 0; p < PLEN; p++) acc = fmaf(hv[p], pw[p*DMODEL + t], acc);
    g_e[((size_t)m*NSEQ + n)*DMODEL + t] = acc;
}

// ---------------- 3. weight pre-split into bf16-pair images ----------------
// B image per (bx,kt): 128 n x 4 float4-slots {H(p),H(p+4),L(p),L(p+4)} indexed (n*4 + (p&3))
__global__ void k_wsplit(const float* __restrict__ in_w, const float* __restrict__ out_w) {
    int idx = blockIdx.x*256 + threadIdx.x;
    if (idx < NLAYERS*32768) {               // in_w: 64 kpairs x 512 n per layer
        int l = idx >> 15;
        int e = idx & 32767;
        int pg = e >> 9, n = e & 511;        // pg 0..63
        const float* W = in_w + (size_t)l*65536;
        float v0 = W[(2*pg)*512 + n];
        float v1 = W[(2*pg+1)*512 + n];
        unsigned hp, lp; bf16split(v0, v1, hp, lp);
        int bx = n >> 7, nl = n & 127;
        int kt = pg >> 3, pl = pg & 7;
        int slotH = (pl >> 2) & 1;
        size_t base = (size_t)l*65536 + (size_t)(bx*8 + kt)*2048 + (size_t)(nl*4 + (pl & 3))*4;
        g_wins[base + slotH]     = hp;
        g_wins[base + 2 + slotH] = lp;
    } else {
        int idx2 = idx - NLAYERS*32768;
        if (idx2 < NLAYERS*16384) {          // out_w: 128 kpairs x 128 n per layer
            int l = idx2 >> 14;
            int e = idx2 & 16383;
            int pg = e >> 7, n = e & 127;    // pg 0..127
            const float* W = out_w + (size_t)l*32768;
            float v0 = W[(2*pg)*128 + n];
            float v1 = W[(2*pg+1)*128 + n];
            unsigned hp, lp; bf16split(v0, v1, hp, lp);
            int kt = pg >> 3, pl = pg & 7;
            int slotH = (pl >> 2) & 1;
            size_t base = (size_t)l*32768 + (size_t)kt*2048 + (size_t)(n*4 + (pl & 3))*4;
            g_wouts[base + slotH]     = hp;
            g_wouts[base + 2 + slotH] = lp;
        }
    }
}

// ---------------- 4. per-row rms factor ----------------
__global__ void k_rms() {
    int warp = threadIdx.x >> 5, lane = threadIdx.x & 31;
    int r = blockIdx.x*8 + warp;
    const float4* p = (const float4*)(g_e + (size_t)r*DMODEL);
    float4 v = p[lane];
    float s = v.x*v.x + v.y*v.y + v.z*v.z + v.w*v.w;
#pragma unroll
    for (int o = 16; o; o >>= 1) s += __shfl_xor_sync(0xffffffff, s, o);
    if (lane == 0) g_rstd[r] = rsqrtf(s*(1.f/DMODEL) + 1e-5f);
}

// ---------------- 5. bf16x2 (3-product) tensor-core GEMM ----------------
// MODE 0: g_uz = (rms(e)*norm_w) @ in_w  (K=128, N=512)
// MODE 1: g_e += y @ out_w               (K=256, N=128)
template<int MODE>
__global__ __launch_bounds__(256, 2) void k_gemm_tc(const float* __restrict__ A,
                                                    const float* __restrict__ colScale,
                                                    const unsigned* __restrict__ Bp,
                                                    float* __restrict__ C) {
    constexpr int N  = (MODE == 0) ? 512 : 128;
    constexpr int K  = (MODE == 0) ? 128 : 256;
    constexpr int KT = K/16;

    __shared__ __align__(16) unsigned AsH[1024], AsL[1024], Bs[2048];

    int tid = threadIdx.x;
    int wid = tid >> 5, lane = tid & 31;
    int wm = wid >> 2, wn = wid & 3;          // 2x4 warps, warp tile 64x32
    int g = lane >> 2, tig = lane & 3;
    int row0 = blockIdx.y * 128;
    int bx = blockIdx.x;
    const float4* Bg = (const float4*)Bp + (size_t)bx*KT*512;

    float acc[4][4][4];
#pragma unroll
    for (int mt = 0; mt < 4; mt++)
#pragma unroll
        for (int nt = 0; nt < 4; nt++)
#pragma unroll
            for (int j = 0; j < 4; j++) acc[mt][nt][j] = 0.f;

    int rA = tid >> 2;
    int kq = (tid & 3)*4;
    int p0 = kq >> 1;                          // first pair index (0..7), p0 even

    for (int kt = 0; kt < KT; kt++) {
        int k0 = kt*16;
        // A stage: fp32 -> scale -> bf16 hi/lo pairs -> permuted smem
#pragma unroll
        for (int s = 0; s < 2; s++) {
            int r = rA + s*64;
            float4 v4 = *(const float4*)&A[(size_t)(row0 + r)*K + k0 + kq];
            float vv[4] = {v4.x, v4.y, v4.z, v4.w};
            if (MODE == 0) {
                float rs = g_rstd[row0 + r];
#pragma unroll
                for (int j = 0; j < 4; j++) vv[j] *= rs * colScale[k0 + kq + j];
            }
            int rg = (r & 7) | ((r >> 4) << 3);
            int rb3 = (r >> 3) & 1;
            int sw = (rg >> 1) & 3;
            unsigned h0, l0, h1, l1;
            bf16split(vv[0], vv[1], h0, l0);
            bf16split(vv[2], vv[3], h1, l1);
            {
                int pp = p0;
                int addr = rg*16 + (((pp & 3) ^ sw) << 2) + (rb3 | (((pp >> 2) & 1) << 1));
                AsH[addr] = h0; AsL[addr] = l0;
            }
            {
                int pp = p0 + 1;
                int addr = rg*16 + (((pp & 3) ^ sw) << 2) + (rb3 | (((pp >> 2) & 1) << 1));
                AsH[addr] = h1; AsL[addr] = l1;
            }
        }
        // B stage: verbatim copy of pre-packed tile (512 float4)
        {
            const float4* src = Bg + (size_t)kt*512;
            float4* dst = (float4*)Bs;
            dst[tid]       = src[tid];
            dst[tid + 256] = src[tid + 256];
        }
        __syncthreads();
        // compute: one pass covers the full 16-k tile (8 pairs)
        {
            int swg = (g >> 1) & 3;
            int txA = tig ^ swg;
            uint4 fH[4], fL[4];
#pragma unroll
            for (int mt = 0; mt < 4; mt++) {
                int rg = g | ((wm*4 + mt) << 3);
                fH[mt] = ((const uint4*)AsH)[rg*4 + txA];
                fL[mt] = ((const uint4*)AsL)[rg*4 + txA];
            }
#pragma unroll
            for (int nt = 0; nt < 4; nt++) {
                int nb = wn*32 + nt*8 + g;
                uint4 fB = ((const uint4*)Bs)[nb*4 + tig];
                unsigned bH[2] = {fB.x, fB.y};
                unsigned bL[2] = {fB.z, fB.w};
#pragma unroll
                for (int mt = 0; mt < 4; mt++) {
                    mma_bf16(acc[mt][nt], (const unsigned*)&fH[mt], bH);
                    mma_bf16(acc[mt][nt], (const unsigned*)&fL[mt], bH);
                    mma_bf16(acc[mt][nt], (const unsigned*)&fH[mt], bL);
                }
            }
        }
        __syncthreads();
    }
#pragma unroll
    for (int mt = 0; mt < 4; mt++) {
#pragma unroll
        for (int nt = 0; nt < 4; nt++) {
            int r = row0 + wm*64 + mt*16 + g;
            int c = bx*128 + wn*32 + nt*8 + tig*2;
            float* p0c = &C[(size_t)r*N + c];
            float* p1c = &C[(size_t)(r+8)*N + c];
            if (MODE == 1) {
                p0c[0] += acc[mt][nt][0]; p0c[1] += acc[mt][nt][1];
                p1c[0] += acc[mt][nt][2]; p1c[1] += acc[mt][nt][3];
            } else {
                p0c[0] = acc[mt][nt][0]; p0c[1] = acc[mt][nt][1];
                p1c[0] = acc[mt][nt][2]; p1c[1] = acc[mt][nt][3];
            }
        }
    }
}

// ---------------- 6. fused conv+silu + xproj + dt + scan + silu(z) ----------------
// smem: xwT[40][260] + uS[32][260] + zS[32][260] + dbcS[32][40] = 113 KB dyn
#define SMEM_MID ((40*260 + 32*260 + 32*260 + 32*40)*4)

__global__ __launch_bounds__(256, 2) void k_mid(
    const float* __restrict__ xw, const float* __restrict__ dtw, const float* __restrict__ dtb,
    const float* __restrict__ cw, const float* __restrict__ cb,
    const float* __restrict__ alog, const float* __restrict__ dp)
{
    extern __shared__ float sm[];
    float* xwT  = sm;                   // [40][260]
    float* uS   = sm + 40*260;          // [32][260]
    float* zS   = uS + 32*260;          // [32][260]
    float* dbcS = zS + 32*260;          // [32][40]

    int m = blockIdx.x, tid = threadIdx.x;
    int rloc = tid >> 3, cg = tid & 7;

    for (int i = tid; i < 256*40; i += 256) {
        int k = i/40, c = i - k*40;
        xwT[c*260 + k] = xw[i];
    }

    float w0 = cw[tid*4+0], w1 = cw[tid*4+1], w2 = cw[tid*4+2], w3 = cw[tid*4+3];
    float cbv = cb[tid];
    float dw[8];
#pragma unroll
    for (int k = 0; k < 8; k++) dw[k] = dtw[k*DI2 + tid];
    float db = dtb[tid];
    float A[16];
#pragma unroll
    for (int s = 0; s < 16; s++) A[s] = -__expf(alog[tid*16 + s]);
    float A0 = A[0];
    bool fast = true;
#pragma unroll
    for (int s = 1; s < 16; s++) {
        float tgt = (float)(s+1)*A0;
        if (fabsf(A[s] - tgt) > 1e-4f*fabsf(tgt)) fast = false;
    }
    float Dv = dp[tid];
    float h[16];
#pragma unroll
    for (int s = 0; s < 16; s++) h[s] = 0.f;
    float x0 = 0.f, x1 = 0.f, x2 = 0.f;
    const float* uz = g_uz + (size_t)m*NSEQ*512;
    float* yp = g_y + (size_t)m*NSEQ*DI2;
    __syncthreads();

    for (int n0 = 0; n0 < NSEQ; n0 += 32) {
        int CN = min(32, NSEQ - n0);
        // --- batched loads: u chunk -> regs, z chunk -> smem ---
        float xv[32];
#pragma unroll
        for (int n = 0; n < 32; n++)
            xv[n] = (n < CN) ? uz[(size_t)(n0+n)*512 + tid] : 0.f;
#pragma unroll
        for (int n = 0; n < 32; n++)
            zS[n*260 + tid] = (n < CN) ? uz[(size_t)(n0+n)*512 + DI2 + tid] : 0.f;
        // --- conv + silu from registers ---
#pragma unroll
        for (int n = 0; n < 32; n++) {
            float v = fmaf(x0, w0, fmaf(x1, w1, fmaf(x2, w2, fmaf(xv[n], w3, cbv))));
            uS[n*260 + tid] = v * (1.f/(1.f + __expf(-v)));
            x0 = x1; x1 = x2; x2 = xv[n];
        }
        __syncthreads();
        // --- xproj 256 -> 40, vectorized ---
        if (rloc < CN) {
            float acc5[5] = {0.f, 0.f, 0.f, 0.f, 0.f};
            const float4* ur4 = (const float4*)(uS + rloc*260);
#pragma unroll 8
            for (int k4 = 0; k4 < 64; k4++) {
                float4 a4 = ur4[k4];
#pragma unroll
                for (int u = 0; u < 5; u++) {
                    float4 w4 = ((const float4*)(xwT + (cg*5 + u)*260))[k4];
                    acc5[u] += a4.x*w4.x + a4.y*w4.y + a4.z*w4.z + a4.w*w4.w;
                }
            }
#pragma unroll
            for (int u = 0; u < 5; u++) dbcS[rloc*40 + cg*5 + u] = acc5[u];
        }
        __syncthreads();
        // --- delta + scan + silu(z) ---
        for (int n = 0; n < CN; n++) {
            const float4* dbc4 = (const float4*)(dbcS + n*40);
            float dt[8];
            *(float4*)&dt[0] = dbc4[0]; *(float4*)&dt[4] = dbc4[1];
            float bb[16], cc[16];
            *(float4*)&bb[0]  = dbc4[2]; *(float4*)&bb[4]  = dbc4[3];
            *(float4*)&bb[8]  = dbc4[4]; *(float4*)&bb[12] = dbc4[5];
            *(float4*)&cc[0]  = dbc4[6]; *(float4*)&cc[4]  = dbc4[7];
            *(float4*)&cc[8]  = dbc4[8]; *(float4*)&cc[12] = dbc4[9];
            float sdt = db;
#pragma unroll
            for (int k = 0; k < 8; k++) sdt = fmaf(dt[k], dw[k], sdt);
            float d = (sdt > 20.f) ? sdt : log1pf(__expf(sdt));
            float u = uS[n*260 + tid];
            float dlu = d*u;
            float a0 = 0.f, a1 = 0.f, a2 = 0.f, a3 = 0.f;
            if (fast) {
                float q = __expf(d*A0);
                float q2 = q*q, q3 = q2*q, q4 = q2*q2;
                float q8 = q4*q4, q12 = q8*q4;
                float pl[4] = {q, q2, q3, q4};
                float pe[4] = {1.f, q4, q8, q12};
#pragma unroll
                for (int s = 0; s < 16; s++) {
                    float p = pe[s>>2]*pl[s&3];
                    h[s] = fmaf(p, h[s], dlu*bb[s]);
                    float t = h[s]*cc[s];
                    if      ((s&3) == 0) a0 += t;
                    else if ((s&3) == 1) a1 += t;
                    else if ((s&3) == 2) a2 += t;
                    else                 a3 += t;
                }
            } else {
#pragma unroll
                for (int s = 0; s < 16; s++) {
                    float dA = __expf(d*A[s]);
                    h[s] = fmaf(dA, h[s], dlu*bb[s]);
                    float t = h[s]*cc[s];
                    if      ((s&3) == 0) a0 += t;
                    else if ((s&3) == 1) a1 += t;
                    else if ((s&3) == 2) a2 += t;
                    else                 a3 += t;
                }
            }
            float accy = (a0 + a1) + (a2 + a3);
            float z = zS[n*260 + tid];
            float sz = z / (1.f + __expf(-z));
            yp[(size_t)(n0+n)*DI2 + tid] = (accy + u*Dv) * sz;
        }
        __syncthreads();
    }
}

// ---------------- 7. final rms + bb dot ----------------
__global__ void k_final(const float* __restrict__ fnw, const float* __restrict__ bbw,
                        const float* __restrict__ bbb) {
    int m = blockIdx.x, t = threadIdx.x;   // 128 threads
    int w = t >> 5, lane = t & 31;
    __shared__ float rstdS[NSEQ];
    for (int n = w; n < NSEQ; n += 4) {
        const float* p = g_e + ((size_t)m*NSEQ + n)*DMODEL;
        float s = 0.f;
#pragma unroll
        for (int i = 0; i < 4; i++) { float v = p[lane + 32*i]; s = fmaf(v, v, s); }
#pragma unroll
        for (int o = 16; o; o >>= 1) s += __shfl_xor_sync(0xffffffff, s, o);
        if (lane == 0) rstdS[n] = rsqrtf(s*(1.f/DMODEL) + 1e-5f);
    }
    __syncthreads();
    float fn = fnw[t];
    float acc = 0.f;
    const float* ep = g_e + (size_t)m*NSEQ*DMODEL + t;
#pragma unroll 4
    for (int n = 0; n < NSEQ; n++)
        acc = fmaf(ep[(size_t)n*DMODEL]*rstdS[n]*fn, bbw[n*DMODEL + t], acc);
#pragma unroll
    for (int o = 16; o; o >>= 1) acc += __shfl_xor_sync(0xffffffff, acc, o);
    __shared__ float fr[4];
    if (lane == 0) fr[w] = acc;
    __syncthreads();
    if (t == 0) g_val[m] = fr[0] + fr[1] + fr[2] + fr[3] + bbb[0];
}

// ---------------- 8. head ----------------
__global__ void k_head(const float* __restrict__ hw, const float* __restrict__ hb,
                       float* __restrict__ out) {
    int t = threadIdx.x;  // 64
    int b = t >> 1, o = t & 1;
    float s = hb[o];
    for (int pd = 0; pd < 64; pd++) s = fmaf(g_val[b*64 + pd], hw[pd*2 + o], s);
    out[t] = s;
}

// ---------------- launch ----------------
extern "C" void kernel_launch(void* const* d_in, const int* in_sizes, int n_in,
                              void* d_out, int out_size) {
    const float* x       = (const float*)d_in[0];
    const float* proj_w  = (const float*)d_in[1];
    const float* proj_b  = (const float*)d_in[2];
    const float* ln_w    = (const float*)d_in[3];
    const float* ln_b    = (const float*)d_in[4];
    const float* patch_w = (const float*)d_in[5];
    const float* patch_b = (const float*)d_in[6];
    const float* in_w    = (const float*)d_in[7];
    const float* conv_w  = (const float*)d_in[8];
    const float* conv_b  = (const float*)d_in[9];
    const float* xproj_w = (const float*)d_in[10];
    const float* dt_w    = (const float*)d_in[11];
    const float* dt_b    = (const float*)d_in[12];
    const float* A_log   = (const float*)d_in[13];
    const float* Dp      = (const float*)d_in[14];
    const float* out_w   = (const float*)d_in[15];
    const float* norm_w  = (const float*)d_in[16];
    const float* fnorm_w = (const float*)d_in[17];
    const float* bb_w    = (const float*)d_in[18];
    const float* bb_b    = (const float*)d_in[19];
    const float* head_w  = (const float*)d_in[20];
    const float* head_b  = (const float*)d_in[21];

    cudaFuncSetAttribute(k_mid, cudaFuncAttributeMaxDynamicSharedMemorySize, SMEM_MID);

    unsigned *d_win, *d_wout;
    float *d_uzp, *d_ep, *d_yp;
    cudaGetSymbolAddress((void**)&d_win, g_wins);
    cudaGetSymbolAddress((void**)&d_wout, g_wouts);
    cudaGetSymbolAddress((void**)&d_uzp, g_uz);
    cudaGetSymbolAddress((void**)&d_ep, g_e);
    cudaGetSymbolAddress((void**)&d_yp, g_y);

    k_proj_ln<<<BATCH*KLEN, 64>>>(x, proj_w, proj_b, ln_w, ln_b);
    k_patch<<<dim3(NSEQ, MROWS), DMODEL>>>(patch_w, patch_b);
    k_wsplit<<<(NLAYERS*(32768+16384))/256, 256>>>(in_w, out_w);

    for (int l = 0; l < NLAYERS; l++) {
        k_rms<<<RTOT/8, 256>>>();
        k_gemm_tc<0><<<dim3(4, RTOT/128), 256>>>(d_ep, norm_w + l*DMODEL,
                                                 d_win + (size_t)l*65536, d_uzp);
        k_mid<<<MROWS, 256, SMEM_MID>>>(xproj_w + l*DI2*40, dt_w + l*DTRANK*DI2, dt_b + l*DI2,
                                        conv_w + l*DI2*DCONV, conv_b + l*DI2,
                                        A_log + l*DI2*DSTATE, Dp + l*DI2);
        k_gemm_tc<1><<<dim3(1, RTOT/128), 256>>>(d_yp, nullptr,
                                                 d_wout + (size_t)l*32768, d_ep);
    }

    k_final<<<MROWS, DMODEL>>>(fnorm_w, bb_w, bb_b);
    k_head<<<1, 64>>>(head_w, head_b, (float*)d_out);
}

// round 11
// speedup vs baseline: 1.8893x; 1.0529x over previous
#include <cuda_runtime.h>
#include <math.h>

// ---------------- problem constants ----------------
#define DIN     32
#define KLEN    512
#define PDIM    64
#define DMODEL  128
#define NLAYERS 4
#define PLEN    8
#define STRIDE  4
#define DI2     256
#define DSTATE  16
#define DCONV   4
#define DTRANK  8
#define NSEQ    127
#define BATCH   32
#define MROWS   (BATCH*PDIM)     // 2048
#define RTOT    (MROWS*NSEQ)     // 260096

// ---------------- scratch ----------------
__device__ float g_h[BATCH*KLEN*PDIM];
__device__ float g_e[RTOT*DMODEL];
__device__ float g_rstd[RTOT];
__device__ float g_uz[RTOT*2*DI2];
__device__ float g_y[RTOT*DI2];
__device__ unsigned g_wins[NLAYERS*65536];   // in_w bf16-pair images
__device__ unsigned g_wouts[NLAYERS*32768];  // out_w bf16-pair images
__device__ float g_val[MROWS];

// ---------------- helpers ----------------
__device__ __forceinline__ unsigned bf16pair(float v0, float v1) {
    unsigned p;
    asm("cvt.rn.bf16x2.f32 %0, %1, %2;" : "=r"(p) : "f"(v1), "f"(v0));
    return p;
}
__device__ __forceinline__ void bf16split(float v0, float v1, unsigned& hp, unsigned& lp) {
    hp = bf16pair(v0, v1);
    float r0 = v0 - __uint_as_float(hp << 16);
    float r1 = v1 - __uint_as_float(hp & 0xffff0000u);
    lp = bf16pair(r0, r1);
}
__device__ __forceinline__ void mma_bf16(float* d, const unsigned* a, const unsigned* b) {
    asm volatile(
        "mma.sync.aligned.m16n8k16.row.col.f32.bf16.bf16.f32 "
        "{%0,%1,%2,%3}, {%4,%5,%6,%7}, {%8,%9}, {%0,%1,%2,%3};\n"
        : "+f"(d[0]), "+f"(d[1]), "+f"(d[2]), "+f"(d[3])
        : "r"(a[0]), "r"(a[1]), "r"(a[2]), "r"(a[3]), "r"(b[0]), "r"(b[1]));
}
__device__ __forceinline__ void cp16(unsigned smem, const void* gptr) {
    asm volatile("cp.async.cg.shared.global [%0], [%1], 16;\n" :: "r"(smem), "l"(gptr));
}
__device__ __forceinline__ unsigned s2u(const void* p) {
    return (unsigned)__cvta_generic_to_shared(p);
}
template<int NN> __device__ __forceinline__ void cpwait() {
    asm volatile("cp.async.wait_group %0;\n" :: "n"(NN));
}

// ---------------- 1. x@proj_w + b, LayerNorm ----------------
__global__ void k_proj_ln(const float* __restrict__ x, const float* __restrict__ pw,
                          const float* __restrict__ pb, const float* __restrict__ lw,
                          const float* __restrict__ lb) {
    int row = blockIdx.x;
    int t = threadIdx.x;
    __shared__ float xs[DIN];
    __shared__ float r1[64], r2[64];
    if (t < DIN) xs[t] = x[row*DIN + t];
    __syncthreads();
    float acc = pb[t];
#pragma unroll
    for (int i = 0; i < DIN; i++) acc = fmaf(xs[i], pw[i*PDIM + t], acc);
    r1[t] = acc; r2[t] = acc*acc;
    __syncthreads();
    for (int o = 32; o; o >>= 1) {
        if (t < o) { r1[t] += r1[t+o]; r2[t] += r2[t+o]; }
        __syncthreads();
    }
    float mu  = r1[0] * (1.f/64.f);
    float var = r2[0] * (1.f/64.f) - mu*mu;
    g_h[row*PDIM + t] = (acc - mu) * rsqrtf(var + 1e-5f) * lw[t] + lb[t];
}

// ---------------- 2. patch embed ----------------
__global__ void k_patch(const float* __restrict__ pw, const float* __restrict__ pb) {
    int n = blockIdx.x, m = blockIdx.y;
    int t = threadIdx.x;
    __shared__ float hv[PLEN];
    int b = m >> 6, pd = m & 63;
    if (t < PLEN) hv[t] = g_h[(b*KLEN + n*STRIDE + t)*PDIM + pd];
    __syncthreads();
    float acc = pb[t];
#pragma unroll
    for (int p = 0; p < PLEN; p++) acc = fmaf(hv[p], pw[p*DMODEL + t], acc);
    g_e[((size_t)m*NSEQ + n)*DMODEL + t] = acc;
}

// ---------------- 3. weight pre-split into bf16-pair images ----------------
__global__ void k_wsplit(const float* __restrict__ in_w, const float* __restrict__ out_w) {
    int idx = blockIdx.x*256 + threadIdx.x;
    if (idx < NLAYERS*32768) {               // in_w: 64 kpairs x 512 n per layer
        int l = idx >> 15;
        int e = idx & 32767;
        int pg = e >> 9, n = e & 511;
        const float* W = in_w + (size_t)l*65536;
        float v0 = W[(2*pg)*512 + n];
        float v1 = W[(2*pg+1)*512 + n];
        unsigned hp, lp; bf16split(v0, v1, hp, lp);
        int bx = n >> 7, nl = n & 127;
        int kt = pg >> 3, pl = pg & 7;
        int slotH = (pl >> 2) & 1;
        size_t base = (size_t)l*65536 + (size_t)(bx*8 + kt)*2048 + (size_t)(nl*4 + (pl & 3))*4;
        g_wins[base + slotH]     = hp;
        g_wins[base + 2 + slotH] = lp;
    } else {
        int idx2 = idx - NLAYERS*32768;
        if (idx2 < NLAYERS*16384) {          // out_w: 128 kpairs x 128 n per layer
            int l = idx2 >> 14;
            int e = idx2 & 16383;
            int pg = e >> 7, n = e & 127;
            const float* W = out_w + (size_t)l*32768;
            float v0 = W[(2*pg)*128 + n];
            float v1 = W[(2*pg+1)*128 + n];
            unsigned hp, lp; bf16split(v0, v1, hp, lp);
            int kt = pg >> 3, pl = pg & 7;
            int slotH = (pl >> 2) & 1;
            size_t base = (size_t)l*32768 + (size_t)kt*2048 + (size_t)(n*4 + (pl & 3))*4;
            g_wouts[base + slotH]     = hp;
            g_wouts[base + 2 + slotH] = lp;
        }
    }
}

// ---------------- 4. per-row rms factor (layer 0 only) ----------------
__global__ void k_rms() {
    int warp = threadIdx.x >> 5, lane = threadIdx.x & 31;
    int r = blockIdx.x*8 + warp;
    const float4* p = (const float4*)(g_e + (size_t)r*DMODEL);
    float4 v = p[lane];
    float s = v.x*v.x + v.y*v.y + v.z*v.z + v.w*v.w;
#pragma unroll
    for (int o = 16; o; o >>= 1) s += __shfl_xor_sync(0xffffffff, s, o);
    if (lane == 0) g_rstd[r] = rsqrtf(s*(1.f/DMODEL) + 1e-5f);
}

// ---------------- 5. bf16x2 (3-product) GEMM, cp.async double-buffered ----------------
// MODE 0: g_uz = (rms(e)*norm_w) @ in_w  (K=128, N=512)
// MODE 1: g_e += y @ out_w; epilogue writes g_rstd of the new g_e rows
template<int MODE>
__global__ __launch_bounds__(256, 2) void k_gemm_tc(const float* __restrict__ A,
                                                    const float* __restrict__ colScale,
                                                    const unsigned* __restrict__ Bp,
                                                    float* __restrict__ C) {
    constexpr int N  = (MODE == 0) ? 512 : 128;
    constexpr int K  = (MODE == 0) ? 128 : 256;
    constexpr int KT = K/16;

    __shared__ __align__(16) unsigned AsH[2][1024], AsL[2][1024], Bs[2][2048];

    int tid = threadIdx.x;
    int wid = tid >> 5, lane = tid & 31;
    int wm = wid >> 2, wn = wid & 3;          // 2x4 warps, warp tile 64x32
    int g = lane >> 2, tig = lane & 3;
    int row0 = blockIdx.y * 128;
    int bx = blockIdx.x;
    const float4* Bg = (const float4*)Bp + (size_t)bx*KT*512;

    float acc[4][4][4];
#pragma unroll
    for (int mt = 0; mt < 4; mt++)
#pragma unroll
        for (int nt = 0; nt < 4; nt++)
#pragma unroll
            for (int j = 0; j < 4; j++) acc[mt][nt][j] = 0.f;

    int rA = tid >> 2;
    int kq = (tid & 3)*4;
    int p0 = kq >> 1;                          // first pair index (even)

    // A store addressing (sw, rb3 invariant under r -> r+64)
    int rg0 = (rA & 7) | ((rA >> 4) << 3);
    int rb3 = (rA >> 3) & 1;
    int sw  = (rg0 >> 1) & 3;
    int a0 = (((p0 & 3) ^ sw) << 2) + (rb3 | (((p0 >> 2) & 1) << 1));
    int p1 = p0 + 1;
    int a1 = (((p1 & 3) ^ sw) << 2) + (rb3 | (((p1 >> 2) & 1) << 1));

    float rs0 = 1.f, rs1 = 1.f;
    if (MODE == 0) { rs0 = g_rstd[row0 + rA]; rs1 = g_rstd[row0 + rA + 64]; }

    // preload tile 0
    cp16(s2u(&Bs[0][tid*4]),       Bg + tid);
    cp16(s2u(&Bs[0][(tid+256)*4]), Bg + tid + 256);
    asm volatile("cp.async.commit_group;\n");
    float4 pa0 = *(const float4*)&A[(size_t)(row0 + rA)*K + kq];
    float4 pa1 = *(const float4*)&A[(size_t)(row0 + rA + 64)*K + kq];

    for (int kt = 0; kt < KT; kt++) {
        int cur = kt & 1, nxt = cur ^ 1;
        bool pre = (kt + 1 < KT);
        if (pre) {
            const float4* src = Bg + (size_t)(kt+1)*512;
            cp16(s2u(&Bs[nxt][tid*4]),       src + tid);
            cp16(s2u(&Bs[nxt][(tid+256)*4]), src + tid + 256);
            asm volatile("cp.async.commit_group;\n");
        }
        float4 na0 = pa0, na1 = pa1;
        if (pre) {
            int k0n = (kt+1)*16;
            na0 = *(const float4*)&A[(size_t)(row0 + rA)*K + k0n + kq];
            na1 = *(const float4*)&A[(size_t)(row0 + rA + 64)*K + k0n + kq];
        }
        // transform current A tile -> As[cur]
        {
            float4 cs = make_float4(1.f, 1.f, 1.f, 1.f);
            if (MODE == 0) cs = *(const float4*)&colScale[kt*16 + kq];
            {
                float v0 = pa0.x, v1 = pa0.y, v2 = pa0.z, v3 = pa0.w;
                if (MODE == 0) { v0 *= rs0*cs.x; v1 *= rs0*cs.y; v2 *= rs0*cs.z; v3 *= rs0*cs.w; }
                unsigned h0, l0, h1, l1;
                bf16split(v0, v1, h0, l0);
                bf16split(v2, v3, h1, l1);
                AsH[cur][rg0*16 + a0] = h0; AsL[cur][rg0*16 + a0] = l0;
                AsH[cur][rg0*16 + a1] = h1; AsL[cur][rg0*16 + a1] = l1;
            }
            {
                float v0 = pa1.x, v1 = pa1.y, v2 = pa1.z, v3 = pa1.w;
                if (MODE == 0) { v0 *= rs1*cs.x; v1 *= rs1*cs.y; v2 *= rs1*cs.z; v3 *= rs1*cs.w; }
                unsigned h0, l0, h1, l1;
                bf16split(v0, v1, h0, l0);
                bf16split(v2, v3, h1, l1);
                int rg1 = rg0 + 32;
                AsH[cur][rg1*16 + a0] = h0; AsL[cur][rg1*16 + a0] = l0;
                AsH[cur][rg1*16 + a1] = h1; AsL[cur][rg1*16 + a1] = l1;
            }
        }
        if (pre) cpwait<1>(); else cpwait<0>();
        __syncthreads();
        // compute
        {
            int swg = (g >> 1) & 3;
            int txA = tig ^ swg;
            uint4 fH[4], fL[4];
#pragma unroll
            for (int mt = 0; mt < 4; mt++) {
                int rg = g | ((wm*4 + mt) << 3);
                fH[mt] = ((const uint4*)AsH[cur])[rg*4 + txA];
                fL[mt] = ((const uint4*)AsL[cur])[rg*4 + txA];
            }
#pragma unroll
            for (int nt = 0; nt < 4; nt++) {
                int nb = wn*32 + nt*8 + g;
                uint4 fB = ((const uint4*)Bs[cur])[nb*4 + tig];
                unsigned bH[2] = {fB.x, fB.y};
                unsigned bL[2] = {fB.z, fB.w};
#pragma unroll
                for (int mt = 0; mt < 4; mt++) {
                    mma_bf16(acc[mt][nt], (const unsigned*)&fH[mt], bH);
                    mma_bf16(acc[mt][nt], (const unsigned*)&fL[mt], bH);
                    mma_bf16(acc[mt][nt], (const unsigned*)&fH[mt], bL);
                }
            }
        }
        __syncthreads();
        pa0 = na0; pa1 = na1;
    }

    if (MODE == 0) {
#pragma unroll
        for (int mt = 0; mt < 4; mt++) {
#pragma unroll
            for (int nt = 0; nt < 4; nt++) {
                int r = row0 + wm*64 + mt*16 + g;
                int c = bx*128 + wn*32 + nt*8 + tig*2;
                float* pc0 = &C[(size_t)r*N + c];
                float* pc1 = &C[(size_t)(r+8)*N + c];
                pc0[0] = acc[mt][nt][0]; pc0[1] = acc[mt][nt][1];
                pc1[0] = acc[mt][nt][2]; pc1[1] = acc[mt][nt][3];
            }
        }
    } else {
        // += epilogue + fused rstd of the updated rows
        float* rsm = (float*)AsH;            // 128 rows x 4 warp-col partials
        float sq[4][2];
#pragma unroll
        for (int mt = 0; mt < 4; mt++) { sq[mt][0] = 0.f; sq[mt][1] = 0.f; }
#pragma unroll
        for (int mt = 0; mt < 4; mt++) {
#pragma unroll
            for (int nt = 0; nt < 4; nt++) {
                int r = row0 + wm*64 + mt*16 + g;
                int c = wn*32 + nt*8 + tig*2;
                float* pc0 = &C[(size_t)r*N + c];
                float* pc1 = &C[(size_t)(r+8)*N + c];
                float f00 = pc0[0] + acc[mt][nt][0];
                float f01 = pc0[1] + acc[mt][nt][1];
                float f10 = pc1[0] + acc[mt][nt][2];
                float f11 = pc1[1] + acc[mt][nt][3];
                pc0[0] = f00; pc0[1] = f01;
                pc1[0] = f10; pc1[1] = f11;
                sq[mt][0] += f00*f00 + f01*f01;
                sq[mt][1] += f10*f10 + f11*f11;
            }
        }
#pragma unroll
        for (int mt = 0; mt < 4; mt++) {
#pragma unroll
            for (int hf = 0; hf < 2; hf++) {
                float v = sq[mt][hf];
                v += __shfl_xor_sync(0xffffffff, v, 1);
                v += __shfl_xor_sync(0xffffffff, v, 2);
                if (tig == 0) rsm[(wm*64 + mt*16 + g + hf*8)*4 + wn] = v;
            }
        }
        __syncthreads();
        if (tid < 128) {
            float s = rsm[tid*4] + rsm[tid*4+1] + rsm[tid*4+2] + rsm[tid*4+3];
            g_rstd[row0 + tid] = rsqrtf(s*(1.f/DMODEL) + 1e-5f);
        }
    }
}

// ---------------- 6. fused conv+silu + xproj + dt + scan + silu(z) ----------------
#define SMEM_MID ((40*260 + 32*260 + 32*260 + 32*40)*4)

__global__ __launch_bounds__(256, 2) void k_mid(
    const float* __restrict__ xw, const float* __restrict__ dtw, const float* __restrict__ dtb,
    const float* __restrict__ cw, const float* __restrict__ cb,
    const float* __restrict__ alog, const float* __restrict__ dp)
{
    extern __shared__ float sm[];
    float* xwT  = sm;                   // [40][260]
    float* uS   = sm + 40*260;          // [32][260]
    float* zS   = uS + 32*260;          // [32][260]
    float* dbcS = zS + 32*260;          // [32][40]

    int m = blockIdx.x, tid = threadIdx.x;
    int rloc = tid >> 3, cg = tid & 7;

    for (int i = tid; i < 256*40; i += 256) {
        int k = i/40, c = i - k*40;
        xwT[c*260 + k] = xw[i];
    }

    float w0 = cw[tid*4+0], w1 = cw[tid*4+1], w2 = cw[tid*4+2], w3 = cw[tid*4+3];
    float cbv = cb[tid];
    float dw[8];
#pragma unroll
    for (int k = 0; k < 8; k++) dw[k] = dtw[k*DI2 + tid];
    float db = dtb[tid];
    float A[16];
#pragma unroll
    for (int s = 0; s < 16; s++) A[s] = -__expf(alog[tid*16 + s]);
    float A0 = A[0];
    bool fast = true;
#pragma unroll
    for (int s = 1; s < 16; s++) {
        float tgt = (float)(s+1)*A0;
        if (fabsf(A[s] - tgt) > 1e-4f*fabsf(tgt)) fast = false;
    }
    float Dv = dp[tid];
    float h[16];
#pragma unroll
    for (int s = 0; s < 16; s++) h[s] = 0.f;
    float x0 = 0.f, x1 = 0.f, x2 = 0.f;
    const float* uz = g_uz + (size_t)m*NSEQ*512;
    float* yp = g_y + (size_t)m*NSEQ*DI2;
    __syncthreads();

    for (int n0 = 0; n0 < NSEQ; n0 += 32) {
        int CN = min(32, NSEQ - n0);
        float xv[32];
#pragma unroll
        for (int n = 0; n < 32; n++)
            xv[n] = (n < CN) ? uz[(size_t)(n0+n)*512 + tid] : 0.f;
#pragma unroll
        for (int n = 0; n < 32; n++)
            zS[n*260 + tid] = (n < CN) ? uz[(size_t)(n0+n)*512 + DI2 + tid] : 0.f;
#pragma unroll
        for (int n = 0; n < 32; n++) {
            float v = fmaf(x0, w0, fmaf(x1, w1, fmaf(x2, w2, fmaf(xv[n], w3, cbv))));
            uS[n*260 + tid] = v * (1.f/(1.f + __expf(-v)));
            x0 = x1; x1 = x2; x2 = xv[n];
        }
        __syncthreads();
        if (rloc < CN) {
            float acc5[5] = {0.f, 0.f, 0.f, 0.f, 0.f};
            const float4* ur4 = (const float4*)(uS + rloc*260);
#pragma unroll 8
            for (int k4 = 0; k4 < 64; k4++) {
                float4 a4 = ur4[k4];
#pragma unroll
                for (int u = 0; u < 5; u++) {
                    float4 w4 = ((const float4*)(xwT + (cg*5 + u)*260))[k4];
                    acc5[u] += a4.x*w4.x + a4.y*w4.y + a4.z*w4.z + a4.w*w4.w;
                }
            }
#pragma unroll
            for (int u = 0; u < 5; u++) dbcS[rloc*40 + cg*5 + u] = acc5[u];
        }
        __syncthreads();
        for (int n = 0; n < CN; n++) {
            const float4* dbc4 = (const float4*)(dbcS + n*40);
            float dt[8];
            *(float4*)&dt[0] = dbc4[0]; *(float4*)&dt[4] = dbc4[1];
            float bb[16], cc[16];
            *(float4*)&bb[0]  = dbc4[2]; *(float4*)&bb[4]  = dbc4[3];
            *(float4*)&bb[8]  = dbc4[4]; *(float4*)&bb[12] = dbc4[5];
            *(float4*)&cc[0]  = dbc4[6]; *(float4*)&cc[4]  = dbc4[7];
            *(float4*)&cc[8]  = dbc4[8]; *(float4*)&cc[12] = dbc4[9];
            float sdt = db;
#pragma unroll
            for (int k = 0; k < 8; k++) sdt = fmaf(dt[k], dw[k], sdt);
            float d = (sdt > 20.f) ? sdt : log1pf(__expf(sdt));
            float u = uS[n*260 + tid];
            float dlu = d*u;
            float a0 = 0.f, a1 = 0.f, a2 = 0.f, a3 = 0.f;
            if (fast) {
                float q = __expf(d*A0);
                float q2 = q*q, q3 = q2*q, q4 = q2*q2;
                float q8 = q4*q4, q12 = q8*q4;
                float pl[4] = {q, q2, q3, q4};
                float pe[4] = {1.f, q4, q8, q12};
#pragma unroll
                for (int s = 0; s < 16; s++) {
                    float p = pe[s>>2]*pl[s&3];
                    h[s] = fmaf(p, h[s], dlu*bb[s]);
                    float t = h[s]*cc[s];
                    if      ((s&3) == 0) a0 += t;
                    else if ((s&3) == 1) a1 += t;
                    else if ((s&3) == 2) a2 += t;
                    else                 a3 += t;
                }
            } else {
#pragma unroll
                for (int s = 0; s < 16; s++) {
                    float dA = __expf(d*A[s]);
                    h[s] = fmaf(dA, h[s], dlu*bb[s]);
                    float t = h[s]*cc[s];
                    if      ((s&3) == 0) a0 += t;
                    else if ((s&3) == 1) a1 += t;
                    else if ((s&3) == 2) a2 += t;
                    else                 a3 += t;
                }
            }
            float accy = (a0 + a1) + (a2 + a3);
            float z = zS[n*260 + tid];
            float sz = z / (1.f + __expf(-z));
            yp[(size_t)(n0+n)*DI2 + tid] = (accy + u*Dv) * sz;
        }
        __syncthreads();
    }
}

// ---------------- 7. final rms + bb dot ----------------
__global__ void k_final(const float* __restrict__ fnw, const float* __restrict__ bbw,
                        const float* __restrict__ bbb) {
    int m = blockIdx.x, t = threadIdx.x;   // 128 threads
    int w = t >> 5, lane = t & 31;
    __shared__ float rstdS[NSEQ];
    for (int n = w; n < NSEQ; n += 4) {
        const float* p = g_e + ((size_t)m*NSEQ + n)*DMODEL;
        float s = 0.f;
#pragma unroll
        for (int i = 0; i < 4; i++) { float v = p[lane + 32*i]; s = fmaf(v, v, s); }
#pragma unroll
        for (int o = 16; o; o >>= 1) s += __shfl_xor_sync(0xffffffff, s, o);
        if (lane == 0) rstdS[n] = rsqrtf(s*(1.f/DMODEL) + 1e-5f);
    }
    __syncthreads();
    float fn = fnw[t];
    float acc = 0.f;
    const float* ep = g_e + (size_t)m*NSEQ*DMODEL + t;
#pragma unroll 4
    for (int n = 0; n < NSEQ; n++)
        acc = fmaf(ep[(size_t)n*DMODEL]*rstdS[n]*fn, bbw[n*DMODEL + t], acc);
#pragma unroll
    for (int o = 16; o; o >>= 1) acc += __shfl_xor_sync(0xffffffff, acc, o);
    __shared__ float fr[4];
    if (lane == 0) fr[w] = acc;
    __syncthreads();
    if (t == 0) g_val[m] = fr[0] + fr[1] + fr[2] + fr[3] + bbb[0];
}

// ---------------- 8. head ----------------
__global__ void k_head(const float* __restrict__ hw, const float* __restrict__ hb,
                       float* __restrict__ out) {
    int t = threadIdx.x;  // 64
    int b = t >> 1, o = t & 1;
    float s = hb[o];
    for (int pd = 0; pd < 64; pd++) s = fmaf(g_val[b*64 + pd], hw[pd*2 + o], s);
    out[t] = s;
}

// ---------------- launch ----------------
extern "C" void kernel_launch(void* const* d_in, const int* in_sizes, int n_in,
                              void* d_out, int out_size) {
    const float* x       = (const float*)d_in[0];
    const float* proj_w  = (const float*)d_in[1];
    const float* proj_b  = (const float*)d_in[2];
    const float* ln_w    = (const float*)d_in[3];
    const float* ln_b    = (const float*)d_in[4];
    const float* patch_w = (const float*)d_in[5];
    const float* patch_b = (const float*)d_in[6];
    const float* in_w    = (const float*)d_in[7];
    const float* conv_w  = (const float*)d_in[8];
    const float* conv_b  = (const float*)d_in[9];
    const float* xproj_w = (const float*)d_in[10];
    const float* dt_w    = (const float*)d_in[11];
    const float* dt_b    = (const float*)d_in[12];
    const float* A_log   = (const float*)d_in[13];
    const float* Dp      = (const float*)d_in[14];
    const float* out_w   = (const float*)d_in[15];
    const float* norm_w  = (const float*)d_in[16];
    const float* fnorm_w = (const float*)d_in[17];
    const float* bb_w    = (const float*)d_in[18];
    const float* bb_b    = (const float*)d_in[19];
    const float* head_w  = (const float*)d_in[20];
    const float* head_b  = (const float*)d_in[21];

    cudaFuncSetAttribute(k_mid, cudaFuncAttributeMaxDynamicSharedMemorySize, SMEM_MID);

    unsigned *d_win, *d_wout;
    float *d_uzp, *d_ep, *d_yp;
    cudaGetSymbolAddress((void**)&d_win, g_wins);
    cudaGetSymbolAddress((void**)&d_wout, g_wouts);
    cudaGetSymbolAddress((void**)&d_uzp, g_uz);
    cudaGetSymbolAddress((void**)&d_ep, g_e);
    cudaGetSymbolAddress((void**)&d_yp, g_y);

    k_proj_ln<<<BATCH*KLEN, 64>>>(x, proj_w, proj_b, ln_w, ln_b);
    k_patch<<<dim3(NSEQ, MROWS), DMODEL>>>(patch_w, patch_b);
    k_wsplit<<<(NLAYERS*(32768+16384))/256, 256>>>(in_w, out_w);
    k_rms<<<RTOT/8, 256>>>();   // layer 0 only; later layers fused in gemm<1>

    for (int l = 0; l < NLAYERS; l++) {
        k_gemm_tc<0><<<dim3(4, RTOT/128), 256>>>(d_ep, norm_w + l*DMODEL,
                                                 d_win + (size_t)l*65536, d_uzp);
        k_mid<<<MROWS, 256, SMEM_MID>>>(xproj_w + l*DI2*40, dt_w + l*DTRANK*DI2, dt_b + l*DI2,
                                        conv_w + l*DI2*DCONV, conv_b + l*DI2,
                                        A_log + l*DI2*DSTATE, Dp + l*DI2);
        k_gemm_tc<1><<<dim3(1, RTOT/128), 256>>>(d_yp, nullptr,
                                                 d_wout + (size_t)l*32768, d_ep);
    }

    k_final<<<MROWS, DMODEL>>>(fnorm_w, bb_w, bb_b);
    k_head<<<1, 64>>>(head_w, head_b, (float*)d_out);
}

// round 13
// speedup vs baseline: 2.0656x; 1.0933x over previous
#include <cuda_runtime.h>
#include <math.h>

// ---------------- problem constants ----------------
#define DIN     32
#define KLEN    512
#define PDIM    64
#define DMODEL  128
#define NLAYERS 4
#define PLEN    8
#define STRIDE  4
#define DI2     256
#define DSTATE  16
#define DCONV   4
#define DTRANK  8
#define NSEQ    127
#define BATCH   32
#define MROWS   (BATCH*PDIM)     // 2048
#define RTOT    (MROWS*NSEQ)     // 260096

// ---------------- scratch ----------------
__device__ float g_h[BATCH*KLEN*PDIM];
__device__ float g_e[RTOT*DMODEL];
__device__ float g_rstd[RTOT];
__device__ float g_uz[RTOT*2*DI2];
__device__ float g_y[RTOT*DI2];
__device__ unsigned g_wins[NLAYERS*65536];   // in_w bf16-pair images
__device__ unsigned g_wouts[NLAYERS*32768];  // out_w bf16-pair images
__device__ float g_val[MROWS];

// ---------------- helpers ----------------
__device__ __forceinline__ unsigned bf16pair(float v0, float v1) {
    unsigned p;
    asm("cvt.rn.bf16x2.f32 %0, %1, %2;" : "=r"(p) : "f"(v1), "f"(v0));
    return p;
}
__device__ __forceinline__ void bf16split(float v0, float v1, unsigned& hp, unsigned& lp) {
    hp = bf16pair(v0, v1);
    float r0 = v0 - __uint_as_float(hp << 16);
    float r1 = v1 - __uint_as_float(hp & 0xffff0000u);
    lp = bf16pair(r0, r1);
}
__device__ __forceinline__ void mma_bf16(float* d, const unsigned* a, const unsigned* b) {
    asm volatile(
        "mma.sync.aligned.m16n8k16.row.col.f32.bf16.bf16.f32 "
        "{%0,%1,%2,%3}, {%4,%5,%6,%7}, {%8,%9}, {%0,%1,%2,%3};\n"
        : "+f"(d[0]), "+f"(d[1]), "+f"(d[2]), "+f"(d[3])
        : "r"(a[0]), "r"(a[1]), "r"(a[2]), "r"(a[3]), "r"(b[0]), "r"(b[1]));
}
__device__ __forceinline__ void cp16(unsigned smem, const void* gptr) {
    asm volatile("cp.async.cg.shared.global [%0], [%1], 16;\n" :: "r"(smem), "l"(gptr));
}
__device__ __forceinline__ unsigned s2u(const void* p) {
    return (unsigned)__cvta_generic_to_shared(p);
}
template<int NN> __device__ __forceinline__ void cpwait() {
    asm volatile("cp.async.wait_group %0;\n" :: "n"(NN));
}

// ---------------- 1. weight pre-split (launch #0) ----------------
__global__ void k_wsplit(const float* __restrict__ in_w, const float* __restrict__ out_w) {
    int idx = blockIdx.x*256 + threadIdx.x;
    if (idx < NLAYERS*32768) {               // in_w: 64 kpairs x 512 n per layer
        int l = idx >> 15;
        int e = idx & 32767;
        int pg = e >> 9, n = e & 511;
        const float* W = in_w + (size_t)l*65536;
        float v0 = W[(2*pg)*512 + n];
        float v1 = W[(2*pg+1)*512 + n];
        unsigned hp, lp; bf16split(v0, v1, hp, lp);
        int bx = n >> 7, nl = n & 127;
        int kt = pg >> 3, pl = pg & 7;
        int slotH = (pl >> 2) & 1;
        size_t base = (size_t)l*65536 + (size_t)(bx*8 + kt)*2048 + (size_t)(nl*4 + (pl & 3))*4;
        g_wins[base + slotH]     = hp;
        g_wins[base + 2 + slotH] = lp;
    } else {
        int idx2 = idx - NLAYERS*32768;
        if (idx2 < NLAYERS*16384) {          // out_w: 128 kpairs x 128 n per layer
            int l = idx2 >> 14;
            int e = idx2 & 16383;
            int pg = e >> 7, n = e & 127;
            const float* W = out_w + (size_t)l*32768;
            float v0 = W[(2*pg)*128 + n];
            float v1 = W[(2*pg+1)*128 + n];
            unsigned hp, lp; bf16split(v0, v1, hp, lp);
            int kt = pg >> 3, pl = pg & 7;
            int slotH = (pl >> 2) & 1;
            size_t base = (size_t)l*32768 + (size_t)kt*2048 + (size_t)(n*4 + (pl & 3))*4;
            g_wouts[base + slotH]     = hp;
            g_wouts[base + 2 + slotH] = lp;
        }
    }
}

// ---------------- 2. x@proj_w + b, LayerNorm (launch #1) ----------------
__global__ void k_proj_ln(const float* __restrict__ x, const float* __restrict__ pw,
                          const float* __restrict__ pb, const float* __restrict__ lw,
                          const float* __restrict__ lb) {
    int row = blockIdx.x;
    int t = threadIdx.x;
    __shared__ float xs[DIN];
    __shared__ float r1[64], r2[64];
    if (t < DIN) xs[t] = x[row*DIN + t];
    __syncthreads();
    float acc = pb[t];
#pragma unroll
    for (int i = 0; i < DIN; i++) acc = fmaf(xs[i], pw[i*PDIM + t], acc);
    r1[t] = acc; r2[t] = acc*acc;
    __syncthreads();
    for (int o = 32; o; o >>= 1) {
        if (t < o) { r1[t] += r1[t+o]; r2[t] += r2[t+o]; }
        __syncthreads();
    }
    float mu  = r1[0] * (1.f/64.f);
    float var = r2[0] * (1.f/64.f) - mu*mu;
    g_h[row*PDIM + t] = (acc - mu) * rsqrtf(var + 1e-5f) * lw[t] + lb[t];
}

// ---------------- 3. patch embed + fused rms (launch #2) ----------------
__global__ void k_patch(const float* __restrict__ pw, const float* __restrict__ pb) {
    int n = blockIdx.x, m = blockIdx.y;
    int t = threadIdx.x;                 // 0..127 (one full e-row per block)
    int w = t >> 5, lane = t & 31;
    __shared__ float hv[PLEN];
    __shared__ float red[4];
    int b = m >> 6, pd = m & 63;
    if (t < PLEN) hv[t] = g_h[(b*KLEN + n*STRIDE + t)*PDIM + pd];
    __syncthreads();
    float acc = pb[t];
#pragma unroll
    for (int p = 0; p < PLEN; p++) acc = fmaf(hv[p], pw[p*DMODEL + t], acc);
    g_e[((size_t)m*NSEQ + n)*DMODEL + t] = acc;
    float s = acc*acc;
#pragma unroll
    for (int o = 16; o; o >>= 1) s += __shfl_xor_sync(0xffffffff, s, o);
    if (lane == 0) red[w] = s;
    __syncthreads();
    if (t == 0) {
        float ss = red[0] + red[1] + red[2] + red[3];
        g_rstd[(size_t)m*NSEQ + n] = rsqrtf(ss*(1.f/DMODEL) + 1e-5f);
    }
}

// ---------------- 4. bf16x2 (3-product) GEMM, cp.async double-buffered ----------------
// MODE 0: g_uz = (rms(e)*norm_w) @ in_w  (K=128, N=512)  -- launch #3 (profiled)
// MODE 1: g_e += y @ out_w; epilogue writes g_rstd of the new g_e rows
template<int MODE>
__global__ __launch_bounds__(256, 2) void k_gemm_tc(const float* __restrict__ A,
                                                    const float* __restrict__ colScale,
                                                    const unsigned* __restrict__ Bp,
                                                    float* __restrict__ C) {
    constexpr int N  = (MODE == 0) ? 512 : 128;
    constexpr int K  = (MODE == 0) ? 128 : 256;
    constexpr int KT = K/16;

    __shared__ __align__(16) unsigned AsH[2][1024], AsL[2][1024], Bs[2][2048];

    int tid = threadIdx.x;
    int wid = tid >> 5, lane = tid & 31;
    int wm = wid >> 2, wn = wid & 3;          // 2x4 warps, warp tile 64x32
    int g = lane >> 2, tig = lane & 3;
    int row0 = blockIdx.y * 128;
    int bx = blockIdx.x;
    const float4* Bg = (const float4*)Bp + (size_t)bx*KT*512;

    float acc[4][4][4];
#pragma unroll
    for (int mt = 0; mt < 4; mt++)
#pragma unroll
        for (int nt = 0; nt < 4; nt++)
#pragma unroll
            for (int j = 0; j < 4; j++) acc[mt][nt][j] = 0.f;

    int rA = tid >> 2;
    int kq = (tid & 3)*4;
    int p0 = kq >> 1;                          // first pair index (even)

    int rg0 = (rA & 7) | ((rA >> 4) << 3);
    int rb3 = (rA >> 3) & 1;
    int sw  = (rg0 >> 1) & 3;
    int a0 = (((p0 & 3) ^ sw) << 2) + (rb3 | (((p0 >> 2) & 1) << 1));
    int p1 = p0 + 1;
    int a1 = (((p1 & 3) ^ sw) << 2) + (rb3 | (((p1 >> 2) & 1) << 1));

    float rs0 = 1.f, rs1 = 1.f;
    if (MODE == 0) { rs0 = g_rstd[row0 + rA]; rs1 = g_rstd[row0 + rA + 64]; }

    // preload tile 0
    cp16(s2u(&Bs[0][tid*4]),       Bg + tid);
    cp16(s2u(&Bs[0][(tid+256)*4]), Bg + tid + 256);
    asm volatile("cp.async.commit_group;\n");
    float4 pa0 = *(const float4*)&A[(size_t)(row0 + rA)*K + kq];
    float4 pa1 = *(const float4*)&A[(size_t)(row0 + rA + 64)*K + kq];

    for (int kt = 0; kt < KT; kt++) {
        int cur = kt & 1, nxt = cur ^ 1;
        bool pre = (kt + 1 < KT);
        if (pre) {
            const float4* src = Bg + (size_t)(kt+1)*512;
            cp16(s2u(&Bs[nxt][tid*4]),       src + tid);
            cp16(s2u(&Bs[nxt][(tid+256)*4]), src + tid + 256);
            asm volatile("cp.async.commit_group;\n");
        }
        float4 na0 = pa0, na1 = pa1;
        if (pre) {
            int k0n = (kt+1)*16;
            na0 = *(const float4*)&A[(size_t)(row0 + rA)*K + k0n + kq];
            na1 = *(const float4*)&A[(size_t)(row0 + rA + 64)*K + k0n + kq];
        }
        {
            float4 cs = make_float4(1.f, 1.f, 1.f, 1.f);
            if (MODE == 0) cs = *(const float4*)&colScale[kt*16 + kq];
            {
                float v0 = pa0.x, v1 = pa0.y, v2 = pa0.z, v3 = pa0.w;
                if (MODE == 0) { v0 *= rs0*cs.x; v1 *= rs0*cs.y; v2 *= rs0*cs.z; v3 *= rs0*cs.w; }
                unsigned h0, l0, h1, l1;
                bf16split(v0, v1, h0, l0);
                bf16split(v2, v3, h1, l1);
                AsH[cur][rg0*16 + a0] = h0; AsL[cur][rg0*16 + a0] = l0;
                AsH[cur][rg0*16 + a1] = h1; AsL[cur][rg0*16 + a1] = l1;
            }
            {
                float v0 = pa1.x, v1 = pa1.y, v2 = pa1.z, v3 = pa1.w;
                if (MODE == 0) { v0 *= rs1*cs.x; v1 *= rs1*cs.y; v2 *= rs1*cs.z; v3 *= rs1*cs.w; }
                unsigned h0, l0, h1, l1;
                bf16split(v0, v1, h0, l0);
                bf16split(v2, v3, h1, l1);
                int rg1 = rg0 + 32;
                AsH[cur][rg1*16 + a0] = h0; AsL[cur][rg1*16 + a0] = l0;
                AsH[cur][rg1*16 + a1] = h1; AsL[cur][rg1*16 + a1] = l1;
            }
        }
        if (pre) cpwait<1>(); else cpwait<0>();
        __syncthreads();
        {
            int swg = (g >> 1) & 3;
            int txA = tig ^ swg;
            uint4 fH[4], fL[4];
#pragma unroll
            for (int mt = 0; mt < 4; mt++) {
                int rg = g | ((wm*4 + mt) << 3);
                fH[mt] = ((const uint4*)AsH[cur])[rg*4 + txA];
                fL[mt] = ((const uint4*)AsL[cur])[rg*4 + txA];
            }
#pragma unroll
            for (int nt = 0; nt < 4; nt++) {
                int nb = wn*32 + nt*8 + g;
                uint4 fB = ((const uint4*)Bs[cur])[nb*4 + tig];
                unsigned bH[2] = {fB.x, fB.y};
                unsigned bL[2] = {fB.z, fB.w};
#pragma unroll
                for (int mt = 0; mt < 4; mt++) {
                    mma_bf16(acc[mt][nt], (const unsigned*)&fH[mt], bH);
                    mma_bf16(acc[mt][nt], (const unsigned*)&fL[mt], bH);
                    mma_bf16(acc[mt][nt], (const unsigned*)&fH[mt], bL);
                }
            }
        }
        __syncthreads();
        pa0 = na0; pa1 = na1;
    }

    if (MODE == 0) {
#pragma unroll
        for (int mt = 0; mt < 4; mt++) {
#pragma unroll
            for (int nt = 0; nt < 4; nt++) {
                int r = row0 + wm*64 + mt*16 + g;
                int c = bx*128 + wn*32 + nt*8 + tig*2;
                float* pc0 = &C[(size_t)r*N + c];
                float* pc1 = &C[(size_t)(r+8)*N + c];
                pc0[0] = acc[mt][nt][0]; pc0[1] = acc[mt][nt][1];
                pc1[0] = acc[mt][nt][2]; pc1[1] = acc[mt][nt][3];
            }
        }
    } else {
        float* rsm = (float*)AsH;            // 128 rows x 4 warp-col partials
        float sq[4][2];
#pragma unroll
        for (int mt = 0; mt < 4; mt++) { sq[mt][0] = 0.f; sq[mt][1] = 0.f; }
#pragma unroll
        for (int mt = 0; mt < 4; mt++) {
#pragma unroll
            for (int nt = 0; nt < 4; nt++) {
                int r = row0 + wm*64 + mt*16 + g;
                int c = wn*32 + nt*8 + tig*2;
                float* pc0 = &C[(size_t)r*N + c];
                float* pc1 = &C[(size_t)(r+8)*N + c];
                float f00 = pc0[0] + acc[mt][nt][0];
                float f01 = pc0[1] + acc[mt][nt][1];
                float f10 = pc1[0] + acc[mt][nt][2];
                float f11 = pc1[1] + acc[mt][nt][3];
                pc0[0] = f00; pc0[1] = f01;
                pc1[0] = f10; pc1[1] = f11;
                sq[mt][0] += f00*f00 + f01*f01;
                sq[mt][1] += f10*f10 + f11*f11;
            }
        }
#pragma unroll
        for (int mt = 0; mt < 4; mt++) {
#pragma unroll
            for (int hf = 0; hf < 2; hf++) {
                float v = sq[mt][hf];
                v += __shfl_xor_sync(0xffffffff, v, 1);
                v += __shfl_xor_sync(0xffffffff, v, 2);
                if (tig == 0) rsm[(wm*64 + mt*16 + g + hf*8)*4 + wn] = v;
            }
        }
        __syncthreads();
        if (tid < 128) {
            float s = rsm[tid*4] + rsm[tid*4+1] + rsm[tid*4+2] + rsm[tid*4+3];
            g_rstd[row0 + tid] = rsqrtf(s*(1.f/DMODEL) + 1e-5f);
        }
    }
}

// ---------------- 5. fused conv+silu + xproj + dt + scan + silu(z) ----------------
#define SMEM_MID ((40*260 + 32*260 + 32*260 + 32*40)*4)

__global__ __launch_bounds__(256, 2) void k_mid(
    const float* __restrict__ xw, const float* __restrict__ dtw, const float* __restrict__ dtb,
    const float* __restrict__ cw, const float* __restrict__ cb,
    const float* __restrict__ alog, const float* __restrict__ dp)
{
    extern __shared__ float sm[];
    float* xwT  = sm;                   // [40][260]
    float* uS   = sm + 40*260;          // [32][260]
    float* zS   = uS + 32*260;          // [32][260]
    float* dbcS = zS + 32*260;          // [32][40]

    int m = blockIdx.x, tid = threadIdx.x;
    int rloc = tid >> 3, cg = tid & 7;

    for (int i = tid; i < 256*40; i += 256) {
        int k = i/40, c = i - k*40;
        xwT[c*260 + k] = xw[i];
    }

    float w0 = cw[tid*4+0], w1 = cw[tid*4+1], w2 = cw[tid*4+2], w3 = cw[tid*4+3];
    float cbv = cb[tid];
    float dw[8];
#pragma unroll
    for (int k = 0; k < 8; k++) dw[k] = dtw[k*DI2 + tid];
    float db = dtb[tid];
    float A[16];
#pragma unroll
    for (int s = 0; s < 16; s++) A[s] = -__expf(alog[tid*16 + s]);
    float A0 = A[0];
    bool fast = true;
#pragma unroll
    for (int s = 1; s < 16; s++) {
        float tgt = (float)(s+1)*A0;
        if (fabsf(A[s] - tgt) > 1e-4f*fabsf(tgt)) fast = false;
    }
    float Dv = dp[tid];
    float h[16];
#pragma unroll
    for (int s = 0; s < 16; s++) h[s] = 0.f;
    float x0 = 0.f, x1 = 0.f, x2 = 0.f;
    const float* uz = g_uz + (size_t)m*NSEQ*512;
    float* yp = g_y + (size_t)m*NSEQ*DI2;
    __syncthreads();

    for (int n0 = 0; n0 < NSEQ; n0 += 32) {
        int CN = min(32, NSEQ - n0);
        float xv[32];
#pragma unroll
        for (int n = 0; n < 32; n++)
            xv[n] = (n < CN) ? uz[(size_t)(n0+n)*512 + tid] : 0.f;
#pragma unroll
        for (int n = 0; n < 32; n++)
            zS[n*260 + tid] = (n < CN) ? uz[(size_t)(n0+n)*512 + DI2 + tid] : 0.f;
#pragma unroll
        for (int n = 0; n < 32; n++) {
            float v = fmaf(x0, w0, fmaf(x1, w1, fmaf(x2, w2, fmaf(xv[n], w3, cbv))));
            uS[n*260 + tid] = __fdividef(v, 1.f + __expf(-v));
            x0 = x1; x1 = x2; x2 = xv[n];
        }
        __syncthreads();
        if (rloc < CN) {
            float acc5[5] = {0.f, 0.f, 0.f, 0.f, 0.f};
            const float4* ur4 = (const float4*)(uS + rloc*260);
#pragma unroll 8
            for (int k4 = 0; k4 < 64; k4++) {
                float4 a4 = ur4[k4];
#pragma unroll
                for (int u = 0; u < 5; u++) {
                    float4 w4 = ((const float4*)(xwT + (cg*5 + u)*260))[k4];
                    acc5[u] += a4.x*w4.x + a4.y*w4.y + a4.z*w4.z + a4.w*w4.w;
                }
            }
#pragma unroll
            for (int u = 0; u < 5; u++) dbcS[rloc*40 + cg*5 + u] = acc5[u];
        }
        __syncthreads();
#pragma unroll 4
        for (int n = 0; n < 32; n++) {
            if (n < CN) {
                const float4* dbc4 = (const float4*)(dbcS + n*40);
                float dt[8];
                *(float4*)&dt[0] = dbc4[0]; *(float4*)&dt[4] = dbc4[1];
                float bb[16], cc[16];
                *(float4*)&bb[0]  = dbc4[2]; *(float4*)&bb[4]  = dbc4[3];
                *(float4*)&bb[8]  = dbc4[4]; *(float4*)&bb[12] = dbc4[5];
                *(float4*)&cc[0]  = dbc4[6]; *(float4*)&cc[4]  = dbc4[7];
                *(float4*)&cc[8]  = dbc4[8]; *(float4*)&cc[12] = dbc4[9];
                float sdt = db;
#pragma unroll
                for (int k = 0; k < 8; k++) sdt = fmaf(dt[k], dw[k], sdt);
                // fast stable softplus: max(x,0) + log(1 + exp(-|x|))
                float d = fmaxf(sdt, 0.f) + __logf(1.f + __expf(-fabsf(sdt)));
                float u = uS[n*260 + tid];
                float dlu = d*u;
                float a0 = 0.f, a1 = 0.f, a2 = 0.f, a3 = 0.f;
                if (fast) {
                    float q = __expf(d*A0);
                    float q2 = q*q, q3 = q2*q, q4 = q2*q2;
                    float q8 = q4*q4, q12 = q8*q4;
                    float pl[4] = {q, q2, q3, q4};
                    float pe[4] = {1.f, q4, q8, q12};
#pragma unroll
                    for (int s = 0; s < 16; s++) {
                        float p = pe[s>>2]*pl[s&3];
                        h[s] = fmaf(p, h[s], dlu*bb[s]);
                        float t = h[s]*cc[s];
                        if      ((s&3) == 0) a0 += t;
                        else if ((s&3) == 1) a1 += t;
                        else if ((s&3) == 2) a2 += t;
                        else                 a3 += t;
                    }
                } else {
#pragma unroll
                    for (int s = 0; s < 16; s++) {
                        float dA = __expf(d*A[s]);
                        h[s] = fmaf(dA, h[s], dlu*bb[s]);
                        float t = h[s]*cc[s];
                        if      ((s&3) == 0) a0 += t;
                        else if ((s&3) == 1) a1 += t;
                        else if ((s&3) == 2) a2 += t;
                        else                 a3 += t;
                    }
                }
                float accy = (a0 + a1) + (a2 + a3);
                float z = zS[n*260 + tid];
                float sz = __fdividef(z, 1.f + __expf(-z));
                yp[(size_t)(n0+n)*DI2 + tid] = (accy + u*Dv) * sz;
            }
        }
        __syncthreads();
    }
}

// ---------------- 6. final rms + bb dot ----------------
__global__ void k_final(const float* __restrict__ fnw, const float* __restrict__ bbw,
                        const float* __restrict__ bbb) {
    int m = blockIdx.x, t = threadIdx.x;   // 128 threads
    int w = t >> 5, lane = t & 31;
    __shared__ float rstdS[NSEQ];
    for (int n = w; n < NSEQ; n += 4) {
        const float* p = g_e + ((size_t)m*NSEQ + n)*DMODEL;
        float s = 0.f;
#pragma unroll
        for (int i = 0; i < 4; i++) { float v = p[lane + 32*i]; s = fmaf(v, v, s); }
#pragma unroll
        for (int o = 16; o; o >>= 1) s += __shfl_xor_sync(0xffffffff, s, o);
        if (lane == 0) rstdS[n] = rsqrtf(s*(1.f/DMODEL) + 1e-5f);
    }
    __syncthreads();
    float fn = fnw[t];
    float acc = 0.f;
    const float* ep = g_e + (size_t)m*NSEQ*DMODEL + t;
#pragma unroll 4
    for (int n = 0; n < NSEQ; n++)
        acc = fmaf(ep[(size_t)n*DMODEL]*rstdS[n]*fn, bbw[n*DMODEL + t], acc);
#pragma unroll
    for (int o = 16; o; o >>= 1) acc += __shfl_xor_sync(0xffffffff, acc, o);
    __shared__ float fr[4];
    if (lane == 0) fr[w] = acc;
    __syncthreads();
    if (t == 0) g_val[m] = fr[0] + fr[1] + fr[2] + fr[3] + bbb[0];
}

// ---------------- 7. head ----------------
__global__ void k_head(const float* __restrict__ hw, const float* __restrict__ hb,
                       float* __restrict__ out) {
    int t = threadIdx.x;  // 64
    int b = t >> 1, o = t & 1;
    float s = hb[o];
    for (int pd = 0; pd < 64; pd++) s = fmaf(g_val[b*64 + pd], hw[pd*2 + o], s);
    out[t] = s;
}

// ---------------- launch ----------------
extern "C" void kernel_launch(void* const* d_in, const int* in_sizes, int n_in,
                              void* d_out, int out_size) {
    const float* x       = (const float*)d_in[0];
    const float* proj_w  = (const float*)d_in[1];
    const float* proj_b  = (const float*)d_in[2];
    const float* ln_w    = (const float*)d_in[3];
    const float* ln_b    = (const float*)d_in[4];
    const float* patch_w = (const float*)d_in[5];
    const float* patch_b = (const float*)d_in[6];
    const float* in_w    = (const float*)d_in[7];
    const float* conv_w  = (const float*)d_in[8];
    const float* conv_b  = (const float*)d_in[9];
    const float* xproj_w = (const float*)d_in[10];
    const float* dt_w    = (const float*)d_in[11];
    const float* dt_b    = (const float*)d_in[12];
    const float* A_log   = (const float*)d_in[13];
    const float* Dp      = (const float*)d_in[14];
    const float* out_w   = (const float*)d_in[15];
    const float* norm_w  = (const float*)d_in[16];
    const float* fnorm_w = (const float*)d_in[17];
    const float* bb_w    = (const float*)d_in[18];
    const float* bb_b    = (const float*)d_in[19];
    const float* head_w  = (const float*)d_in[20];
    const float* head_b  = (const float*)d_in[21];

    cudaFuncSetAttribute(k_mid, cudaFuncAttributeMaxDynamicSharedMemorySize, SMEM_MID);

    unsigned *d_win, *d_wout;
    float *d_uzp, *d_ep, *d_yp;
    cudaGetSymbolAddress((void**)&d_win, g_wins);
    cudaGetSymbolAddress((void**)&d_wout, g_wouts);
    cudaGetSymbolAddress((void**)&d_uzp, g_uz);
    cudaGetSymbolAddress((void**)&d_ep, g_e);
    cudaGetSymbolAddress((void**)&d_yp, g_y);

    // order chosen so launch #3 (the ncu capture slot) is the hot gemm<0>
    k_wsplit<<<(NLAYERS*(32768+16384))/256, 256>>>(in_w, out_w);
    k_proj_ln<<<BATCH*KLEN, 64>>>(x, proj_w, proj_b, ln_w, ln_b);
    k_patch<<<dim3(NSEQ, MROWS), DMODEL>>>(patch_w, patch_b);   // fused rms

    for (int l = 0; l < NLAYERS; l++) {
        k_gemm_tc<0><<<dim3(4, RTOT/128), 256>>>(d_ep, norm_w + l*DMODEL,
                                                 d_win + (size_t)l*65536, d_uzp);
        k_mid<<<MROWS, 256, SMEM_MID>>>(xproj_w + l*DI2*40, dt_w + l*DTRANK*DI2, dt_b + l*DI2,
                                        conv_w + l*DI2*DCONV, conv_b + l*DI2,
                                        A_log + l*DI2*DSTATE, Dp + l*DI2);
        k_gemm_tc<1><<<dim3(1, RTOT/128), 256>>>(d_yp, nullptr,
                                                 d_wout + (size_t)l*32768, d_ep);
    }

    k_final<<<MROWS, DMODEL>>>(fnorm_w, bb_w, bb_b);
    k_head<<<1, 64>>>(head_w, head_b, (float*)d_out);
}